// round 2
// baseline (speedup 1.0000x reference)
#include <cuda_runtime.h>
#include <cstdint>

#define Bb 4
#define Nn 4096
#define KK 16
#define DP 64
#define DM 128
#define BN (Bb*Nn)

// ---- scratch (device globals: allocation-free) ----
__device__ int   g_knn[BN*KK];     // knn indices
__device__ float g_F [BN*DM];      // f = features@Wf1+bf1
__device__ float g_Q [BN*DM];      // f@Wq
__device__ float g_Kf[BN*DM];      // f@Wk
__device__ float g_Vf[BN*DM];      // f@Wv

// ============================================================
// KNN: one warp per query, per-lane local top-16 + warp merge
// ============================================================
__global__ void __launch_bounds__(256) knn_kernel(const float* __restrict__ xyz)
{
    __shared__ float xs[Nn], ys[Nn], zs[Nn];
    int b = blockIdx.x;
    const float* base = xyz + (size_t)b * Nn * 3;
    for (int j = threadIdx.x; j < Nn * 3; j += blockDim.x) {
        float v = base[j];
        int p = j / 3, c = j - p * 3;
        if (c == 0) xs[p] = v; else if (c == 1) ys[p] = v; else zs[p] = v;
    }
    __syncthreads();

    int warp = threadIdx.x >> 5, lane = threadIdx.x & 31;
    int q0 = blockIdx.y * 32 + warp * 4;

    for (int qi = 0; qi < 4; qi++) {
        int q = q0 + qi;
        float qx = xs[q], qy = ys[q], qz = zs[q];
        float qsq = fmaf(qz, qz, fmaf(qy, qy, qx * qx));

        float bd[KK]; int bi[KK];
        #pragma unroll
        for (int i = 0; i < KK; i++) { bd[i] = 3.4e38f; bi[i] = -1; }

        for (int m = lane; m < Nn; m += 32) {
            float cx = xs[m], cy = ys[m], cz = zs[m];
            float csq = fmaf(cz, cz, fmaf(cy, cy, cx * cx));
            float dot = fmaf(qz, cz, fmaf(qy, cy, qx * cx));
            float d2  = (qsq + csq) - 2.0f * dot;
            if (d2 < bd[KK - 1]) {
                int pos = KK - 1;
                while (pos > 0 && bd[pos - 1] > d2) {
                    bd[pos] = bd[pos - 1]; bi[pos] = bi[pos - 1]; pos--;
                }
                bd[pos] = d2; bi[pos] = m;
            }
        }

        // warp merge: 16 rounds of pick-global-min
        int ptr = 0;
        int keep = 0;
        for (int r = 0; r < KK; r++) {
            float d = (ptr < KK) ? bd[ptr] : 3.4e38f;
            float mn = d;
            #pragma unroll
            for (int off = 16; off; off >>= 1)
                mn = fminf(mn, __shfl_xor_sync(0xffffffffu, mn, off));
            unsigned msk = __ballot_sync(0xffffffffu, d == mn);
            int owner = __ffs(msk) - 1;
            int widx  = __shfl_sync(0xffffffffu, (ptr < KK) ? bi[ptr] : 0, owner);
            if (lane == owner) ptr++;
            if (lane == r) keep = widx;
        }
        if (lane < KK) g_knn[((size_t)b * Nn + q) * KK + lane] = keep;
    }
}

// ============================================================
// Generic row-major linear: out[M,128] = in[M,KD]@W[KD,128] (+bias)
// block: 256 threads, 64-row tile, 4x8 register micro-tiles
// ============================================================
template<int KD>
__global__ void __launch_bounds__(256) linear_kernel(
    const float* __restrict__ in, const float* __restrict__ W,
    const float* __restrict__ bias, float* __restrict__ out)
{
    constexpr int STR = KD + 1;
    __shared__ float s_in[64 * STR];
    int row0 = blockIdx.x * 64;
    int tid = threadIdx.x;

    for (int e = tid; e < 64 * KD; e += 256) {
        int r = e / KD, c = e % KD;
        s_in[r * STR + c] = in[(size_t)(row0 + r) * KD + c];
    }
    __syncthreads();

    int r0 = (tid >> 4) * 4;
    int c0 = (tid & 15) * 8;
    float acc[4][8];
    #pragma unroll
    for (int i = 0; i < 4; i++)
        #pragma unroll
        for (int j = 0; j < 8; j++) acc[i][j] = 0.f;

    #pragma unroll 4
    for (int kk = 0; kk < KD; kk++) {
        float4 w0 = *reinterpret_cast<const float4*>(W + (size_t)kk * DM + c0);
        float4 w1 = *reinterpret_cast<const float4*>(W + (size_t)kk * DM + c0 + 4);
        float wv[8] = {w0.x, w0.y, w0.z, w0.w, w1.x, w1.y, w1.z, w1.w};
        float av[4];
        #pragma unroll
        for (int i = 0; i < 4; i++) av[i] = s_in[(r0 + i) * STR + kk];
        #pragma unroll
        for (int i = 0; i < 4; i++)
            #pragma unroll
            for (int j = 0; j < 8; j++)
                acc[i][j] = fmaf(av[i], wv[j], acc[i][j]);
    }

    float bv[8];
    #pragma unroll
    for (int j = 0; j < 8; j++) bv[j] = bias ? bias[c0 + j] : 0.f;
    #pragma unroll
    for (int i = 0; i < 4; i++)
        #pragma unroll
        for (int j = 0; j < 8; j++)
            out[(size_t)(row0 + r0 + i) * DM + c0 + j] = acc[i][j] + bv[j];
}

// ============================================================
// In-block 64x128 = [64x128]@[128x128] GEMM on smem A, global W
// ============================================================
__device__ __forceinline__ void gemm64(
    const float* __restrict__ As, const float* __restrict__ W,
    const float* __restrict__ bias, float* __restrict__ Cs,
    bool doRelu, int tid)
{
    int r0 = (tid >> 4) * 4;
    int c0 = (tid & 15) * 8;
    float acc[4][8];
    #pragma unroll
    for (int i = 0; i < 4; i++)
        #pragma unroll
        for (int j = 0; j < 8; j++) acc[i][j] = 0.f;

    #pragma unroll 4
    for (int kk = 0; kk < DM; kk++) {
        float4 w0 = *reinterpret_cast<const float4*>(W + (size_t)kk * DM + c0);
        float4 w1 = *reinterpret_cast<const float4*>(W + (size_t)kk * DM + c0 + 4);
        float wv[8] = {w0.x, w0.y, w0.z, w0.w, w1.x, w1.y, w1.z, w1.w};
        float av[4];
        #pragma unroll
        for (int i = 0; i < 4; i++) av[i] = As[(r0 + i) * 129 + kk];
        #pragma unroll
        for (int i = 0; i < 4; i++)
            #pragma unroll
            for (int j = 0; j < 8; j++)
                acc[i][j] = fmaf(av[i], wv[j], acc[i][j]);
    }

    float bv[8];
    #pragma unroll
    for (int j = 0; j < 8; j++) bv[j] = bias[c0 + j];
    #pragma unroll
    for (int i = 0; i < 4; i++)
        #pragma unroll
        for (int j = 0; j < 8; j++) {
            float v = acc[i][j] + bv[j];
            if (doRelu) v = fmaxf(v, 0.f);
            Cs[(r0 + i) * 129 + c0 + j] = v;
        }
}

// ============================================================
// Fused main kernel: 4 points (64 neighbor-rows) per block
// pos-enc MLP -> (q - k + pos) -> gamma MLP -> softmax(K) ->
// weighted sum with (v + pos) -> fc2 + residual
// ============================================================
__global__ void __launch_bounds__(256, 2) main_kernel(
    const float* __restrict__ xyz,  const float* __restrict__ features,
    const float* __restrict__ Wd1,  const float* __restrict__ bd1,
    const float* __restrict__ Wd2,  const float* __restrict__ bd2,
    const float* __restrict__ Wg1,  const float* __restrict__ bg1,
    const float* __restrict__ Wg2,  const float* __restrict__ bg2,
    const float* __restrict__ Wo,   const float* __restrict__ bo,
    float* __restrict__ out)
{
    extern __shared__ float sm[];
    float* bufA = sm;                  // 64*129
    float* bufE = sm + 64 * 129;       // pos_enc (persists)
    float* bufC = sm + 2 * 64 * 129;

    __shared__ int   s_idx[64];
    __shared__ float s_rx[64], s_ry[64], s_rz[64];

    int blk  = blockIdx.x;             // 0..4095
    int b    = blk >> 10;              // N/4 = 1024 tiles per batch
    int tile = blk & 1023;
    int p0   = tile * 4;
    int tid  = threadIdx.x;

    if (tid < 64) {
        int p  = tid >> 4;
        int gp = b * Nn + p0 + p;
        int idx = g_knn[(size_t)gp * KK + (tid & 15)];
        s_idx[tid] = idx;
        int gi = b * Nn + idx;
        s_rx[tid] = xyz[(size_t)gp * 3 + 0] - xyz[(size_t)gi * 3 + 0];
        s_ry[tid] = xyz[(size_t)gp * 3 + 1] - xyz[(size_t)gi * 3 + 1];
        s_rz[tid] = xyz[(size_t)gp * 3 + 2] - xyz[(size_t)gi * 3 + 2];
    }
    __syncthreads();

    // stage 1: bufA = relu(rel @ Wd1 + bd1)   [64,128]
    {
        int c  = tid & 127;
        int rb = tid >> 7;
        float w0 = Wd1[c], w1 = Wd1[DM + c], w2 = Wd1[2 * DM + c], bb = bd1[c];
        for (int r = rb; r < 64; r += 2) {
            float v = fmaf(s_rx[r], w0, fmaf(s_ry[r], w1, fmaf(s_rz[r], w2, bb)));
            bufA[r * 129 + c] = fmaxf(v, 0.f);
        }
    }
    __syncthreads();

    // stage 2: bufE = bufA @ Wd2 + bd2   (pos_enc)
    gemm64(bufA, Wd2, bd2, bufE, false, tid);
    __syncthreads();

    // stage 3: bufA = q - gather(k) + pos_enc
    for (int e = tid; e < 64 * 128; e += 256) {
        int r = e >> 7, c = e & 127;
        int p = r >> 4;
        float qv = g_Q [(size_t)(b * Nn + p0 + p) * DM + c];
        float kv = g_Kf[(size_t)(b * Nn + s_idx[r]) * DM + c];
        bufA[r * 129 + c] = qv - kv + bufE[r * 129 + c];
    }
    __syncthreads();

    // stage 4/5: gamma MLP
    gemm64(bufA, Wg1, bg1, bufC, true, tid);
    __syncthreads();
    gemm64(bufC, Wg2, bg2, bufA, false, tid);
    __syncthreads();

    // stage 6: softmax over K (per point,dim) + weighted sum with (v+pos_enc)
    const float inv_s = 0.08838834764831845f;  // 1/sqrt(128)
    for (int e = tid; e < 4 * 128; e += 256) {
        int p = e >> 7, c = e & 127;
        float mx = -3.4e38f;
        #pragma unroll
        for (int k = 0; k < KK; k++)
            mx = fmaxf(mx, bufA[(p * 16 + k) * 129 + c]);
        float sum = 0.f, acc = 0.f;
        #pragma unroll
        for (int k = 0; k < KK; k++) {
            int r = p * 16 + k;
            float ev = __expf((bufA[r * 129 + c] - mx) * inv_s);
            sum += ev;
            float vv = g_Vf[(size_t)(b * Nn + s_idx[r]) * DM + c] + bufE[r * 129 + c];
            acc = fmaf(ev, vv, acc);
        }
        bufC[p * 129 + c] = acc / sum;
    }
    __syncthreads();

    // stage 7: out = res @ Wo + bo + features   [4,64]
    {
        int p = tid >> 6, j = tid & 63;
        float acc = bo[j];
        #pragma unroll 4
        for (int c = 0; c < 128; c++)
            acc = fmaf(bufC[p * 129 + c], Wo[(size_t)c * DP + j], acc);
        int gp = b * Nn + p0 + p;
        out[(size_t)gp * DP + j] = acc + features[(size_t)gp * DP + j];
    }
}

// ============================================================
extern "C" void kernel_launch(void* const* d_in, const int* in_sizes, int n_in,
                              void* d_out, int out_size)
{
    (void)in_sizes; (void)n_in; (void)out_size;
    const float* xyz      = (const float*)d_in[0];
    const float* features = (const float*)d_in[1];
    const float* Wd1 = (const float*)d_in[2];
    const float* bd1 = (const float*)d_in[3];
    const float* Wd2 = (const float*)d_in[4];
    const float* bd2 = (const float*)d_in[5];
    const float* Wf1 = (const float*)d_in[6];
    const float* bf1 = (const float*)d_in[7];
    const float* Wq  = (const float*)d_in[8];
    const float* Wk  = (const float*)d_in[9];
    const float* Wv  = (const float*)d_in[10];
    const float* Wg1 = (const float*)d_in[11];
    const float* bg1 = (const float*)d_in[12];
    const float* Wg2 = (const float*)d_in[13];
    const float* bg2 = (const float*)d_in[14];
    const float* Wo  = (const float*)d_in[15];
    const float* bo  = (const float*)d_in[16];
    float* out = (float*)d_out;

    float *pF, *pQ, *pK, *pV;
    cudaGetSymbolAddress((void**)&pF, g_F);
    cudaGetSymbolAddress((void**)&pQ, g_Q);
    cudaGetSymbolAddress((void**)&pK, g_Kf);
    cudaGetSymbolAddress((void**)&pV, g_Vf);

    knn_kernel<<<dim3(Bb, Nn / 32), 256>>>(xyz);

    linear_kernel<64> <<<BN / 64, 256>>>(features, Wf1, bf1, pF);
    linear_kernel<128><<<BN / 64, 256>>>(pF, Wq, nullptr, pQ);
    linear_kernel<128><<<BN / 64, 256>>>(pF, Wk, nullptr, pK);
    linear_kernel<128><<<BN / 64, 256>>>(pF, Wv, nullptr, pV);

    size_t shmem = 3 * 64 * 129 * sizeof(float);
    cudaFuncSetAttribute(main_kernel,
                         cudaFuncAttributeMaxDynamicSharedMemorySize, (int)shmem);
    main_kernel<<<BN / 4, 256, shmem>>>(xyz, features,
                                        Wd1, bd1, Wd2, bd2,
                                        Wg1, bg1, Wg2, bg2,
                                        Wo, bo, out);
}

// round 3
// speedup vs baseline: 2.4605x; 2.4605x over previous
#include <cuda_runtime.h>
#include <cstdint>

#define Bb 4
#define Nn 4096
#define KK 16
#define DP 64
#define DM 128
#define BN (Bb*Nn)

// ---- scratch (device globals: allocation-free) ----
__device__ int   g_knn[BN*KK];
__device__ float g_Q [BN*DM];
__device__ float g_Kf[BN*DM];
__device__ float g_Vf[BN*DM];

// ============================================================
// cp.async helpers
// ============================================================
__device__ __forceinline__ void cp16(float* dst_smem, const float* src) {
    uint32_t d = (uint32_t)__cvta_generic_to_shared(dst_smem);
    asm volatile("cp.async.ca.shared.global [%0], [%1], 16;" :: "r"(d), "l"(src) : "memory");
}

// ============================================================
// KNN: one warp per query; register-resident top-16 (NO dynamic
// indexing -> no local-memory spill), shift-based warp merge.
// ============================================================
__global__ void __launch_bounds__(256) knn_kernel(const float* __restrict__ xyz)
{
    __shared__ float xs[Nn], ys[Nn], zs[Nn];
    int b = blockIdx.x;
    const float* base = xyz + (size_t)b * Nn * 3;
    for (int j = threadIdx.x; j < Nn * 3; j += blockDim.x) {
        float v = base[j];
        int p = j / 3, c = j - p * 3;
        if (c == 0) xs[p] = v; else if (c == 1) ys[p] = v; else zs[p] = v;
    }
    __syncthreads();

    int warp = threadIdx.x >> 5, lane = threadIdx.x & 31;
    int q0 = blockIdx.y * 32 + warp * 4;

    for (int qi = 0; qi < 4; qi++) {
        int q = q0 + qi;
        float qx = xs[q], qy = ys[q], qz = zs[q];
        float qsq = fmaf(qz, qz, fmaf(qy, qy, qx * qx));

        float bd[KK]; int bi[KK];
        #pragma unroll
        for (int i = 0; i < KK; i++) { bd[i] = 3.4e38f; bi[i] = -1; }

        for (int m = lane; m < Nn; m += 32) {
            float cx = xs[m], cy = ys[m], cz = zs[m];
            float csq = fmaf(cz, cz, fmaf(cy, cy, cx * cx));
            float dot = fmaf(qz, cz, fmaf(qy, cy, qx * cx));
            float d2  = (qsq + csq) - 2.0f * dot;
            if (d2 < bd[KK - 1]) {
                // sorted-insert via single bubble pass, static indices only
                bd[KK - 1] = d2; bi[KK - 1] = m;
                #pragma unroll
                for (int i = KK - 1; i > 0; i--) {
                    bool sw = bd[i] < bd[i - 1];
                    float td = bd[i - 1]; int ti = bi[i - 1];
                    if (sw) {
                        bd[i - 1] = bd[i]; bi[i - 1] = bi[i];
                        bd[i] = td;        bi[i] = ti;
                    }
                }
            }
        }

        // merge: 16 rounds of extract-min; owner shifts its sorted list down
        int keep = 0;
        #pragma unroll 1
        for (int r = 0; r < KK; r++) {
            float d = bd[0];
            float mn = d;
            #pragma unroll
            for (int off = 16; off; off >>= 1)
                mn = fminf(mn, __shfl_xor_sync(0xffffffffu, mn, off));
            unsigned msk = __ballot_sync(0xffffffffu, d == mn);
            int owner = __ffs(msk) - 1;
            int widx  = __shfl_sync(0xffffffffu, bi[0], owner);
            if (lane == owner) {
                #pragma unroll
                for (int i = 0; i < KK - 1; i++) { bd[i] = bd[i + 1]; bi[i] = bi[i + 1]; }
                bd[KK - 1] = 3.4e38f;
            }
            if (lane == r) keep = widx;
        }
        if (lane < KK) g_knn[((size_t)b * Nn + q) * KK + lane] = keep;
    }
}

// ============================================================
// Staged 64-row GEMM tile: out[64,128] = As[64,KD] @ W[KD,128]
// W double-buffered into smem via cp.async (8 k-rows per chunk).
// NCH = KD/8. ASTR = smem row stride of As. OSTR: 128 -> global
// float4 stores, else scalar smem stores.
// ============================================================
template<int NCH, int ASTR, int OSTR, bool RELU>
__device__ __forceinline__ void gemm_tile(
    const float* __restrict__ As, const float* __restrict__ W,
    const float* __restrict__ bias, float* __restrict__ Out,
    int tid, float* __restrict__ Wbuf)
{
    int r0 = (tid >> 4) * 4;
    int c0 = (tid & 15) * 8;
    float acc[4][8];
    #pragma unroll
    for (int i = 0; i < 4; i++)
        #pragma unroll
        for (int j = 0; j < 8; j++) acc[i][j] = 0.f;

    cp16(Wbuf + tid * 4, W + tid * 4);
    asm volatile("cp.async.commit_group;" ::: "memory");

    #pragma unroll 1
    for (int ch = 0; ch < NCH; ch++) {
        const float* cur = Wbuf + (ch & 1) * 1024;
        if (ch + 1 < NCH) {
            cp16(Wbuf + ((ch + 1) & 1) * 1024 + tid * 4,
                 W + (size_t)(ch + 1) * 1024 + tid * 4);
            asm volatile("cp.async.commit_group;" ::: "memory");
            asm volatile("cp.async.wait_group 1;" ::: "memory");
        } else {
            asm volatile("cp.async.wait_group 0;" ::: "memory");
        }
        __syncthreads();

        #pragma unroll
        for (int k8 = 0; k8 < 8; k8++) {
            const float* wrow = cur + k8 * 128;
            float4 w0 = *reinterpret_cast<const float4*>(wrow + c0);
            float4 w1 = *reinterpret_cast<const float4*>(wrow + c0 + 4);
            float wv[8] = {w0.x, w0.y, w0.z, w0.w, w1.x, w1.y, w1.z, w1.w};
            int kk = ch * 8 + k8;
            float av[4];
            #pragma unroll
            for (int i = 0; i < 4; i++) av[i] = As[(r0 + i) * ASTR + kk];
            #pragma unroll
            for (int i = 0; i < 4; i++)
                #pragma unroll
                for (int j = 0; j < 8; j++)
                    acc[i][j] = fmaf(av[i], wv[j], acc[i][j]);
        }
        __syncthreads();
    }

    float bv[8];
    #pragma unroll
    for (int j = 0; j < 8; j++) bv[j] = bias ? bias[c0 + j] : 0.f;
    #pragma unroll
    for (int i = 0; i < 4; i++) {
        float v[8];
        #pragma unroll
        for (int j = 0; j < 8; j++) {
            v[j] = acc[i][j] + bv[j];
            if (RELU) v[j] = fmaxf(v[j], 0.f);
        }
        if (OSTR == 128) {
            float4* o = reinterpret_cast<float4*>(Out + (size_t)(r0 + i) * OSTR + c0);
            o[0] = make_float4(v[0], v[1], v[2], v[3]);
            o[1] = make_float4(v[4], v[5], v[6], v[7]);
        } else {
            #pragma unroll
            for (int j = 0; j < 8; j++)
                Out[(r0 + i) * OSTR + c0 + j] = v[j];
        }
    }
}

// ============================================================
// Fused projections: f = features@Wf1+bf1 (smem), then q/k/v
// ============================================================
__global__ void __launch_bounds__(256) fqkv_kernel(
    const float* __restrict__ features,
    const float* __restrict__ Wf1, const float* __restrict__ bf1,
    const float* __restrict__ Wq,  const float* __restrict__ Wk,
    const float* __restrict__ Wv)
{
    extern __shared__ float sm[];
    float* s_x  = sm;                 // 64*65
    float* s_f  = sm + 64 * 65;       // 64*129
    float* Wbuf = s_f + 64 * 129;     // 2048

    int row0 = blockIdx.x * 64;
    int tid  = threadIdx.x;

    for (int e = tid; e < 64 * DP; e += 256) {
        int r = e >> 6, c = e & 63;
        s_x[r * 65 + c] = features[(size_t)(row0 + r) * DP + c];
    }
    __syncthreads();

    gemm_tile<8, 65, 129, false>(s_x, Wf1, bf1, s_f, tid, Wbuf);
    gemm_tile<16, 129, 128, false>(s_f, Wq, nullptr, g_Q  + (size_t)row0 * DM, tid, Wbuf);
    gemm_tile<16, 129, 128, false>(s_f, Wk, nullptr, g_Kf + (size_t)row0 * DM, tid, Wbuf);
    gemm_tile<16, 129, 128, false>(s_f, Wv, nullptr, g_Vf + (size_t)row0 * DM, tid, Wbuf);
}

// ============================================================
// Fused main kernel: 4 points (64 neighbor-rows) per block
// ============================================================
__global__ void __launch_bounds__(256, 2) main_kernel(
    const float* __restrict__ xyz,  const float* __restrict__ features,
    const float* __restrict__ Wd1,  const float* __restrict__ bd1,
    const float* __restrict__ Wd2,  const float* __restrict__ bd2,
    const float* __restrict__ Wg1,  const float* __restrict__ bg1,
    const float* __restrict__ Wg2,  const float* __restrict__ bg2,
    const float* __restrict__ Wo,   const float* __restrict__ bo,
    float* __restrict__ out)
{
    extern __shared__ float sm[];
    float* bufA = sm;                  // 64*129
    float* bufE = sm + 64 * 129;       // pos_enc (persists)
    float* bufC = sm + 2 * 64 * 129;
    float* bufW = sm + 3 * 64 * 129;   // 2048 (weight double buffer)

    __shared__ int   s_idx[64];
    __shared__ float s_rx[64], s_ry[64], s_rz[64];

    int blk  = blockIdx.x;
    int b    = blk >> 10;
    int tile = blk & 1023;
    int p0   = tile * 4;
    int tid  = threadIdx.x;

    if (tid < 64) {
        int p  = tid >> 4;
        int gp = b * Nn + p0 + p;
        int idx = g_knn[(size_t)gp * KK + (tid & 15)];
        s_idx[tid] = idx;
        int gi = b * Nn + idx;
        s_rx[tid] = xyz[(size_t)gp * 3 + 0] - xyz[(size_t)gi * 3 + 0];
        s_ry[tid] = xyz[(size_t)gp * 3 + 1] - xyz[(size_t)gi * 3 + 1];
        s_rz[tid] = xyz[(size_t)gp * 3 + 2] - xyz[(size_t)gi * 3 + 2];
    }
    __syncthreads();

    // stage 1: bufA = relu(rel @ Wd1 + bd1)
    {
        int c  = tid & 127;
        int rb = tid >> 7;
        float w0 = Wd1[c], w1 = Wd1[DM + c], w2 = Wd1[2 * DM + c], bb = bd1[c];
        for (int r = rb; r < 64; r += 2) {
            float v = fmaf(s_rx[r], w0, fmaf(s_ry[r], w1, fmaf(s_rz[r], w2, bb)));
            bufA[r * 129 + c] = fmaxf(v, 0.f);
        }
    }
    __syncthreads();

    // stage 2: bufE = bufA @ Wd2 + bd2  (pos_enc)
    gemm_tile<16, 129, 129, false>(bufA, Wd2, bd2, bufE, tid, bufW);
    __syncthreads();

    // stage 3: bufA = q - gather(k) + pos_enc
    for (int e = tid; e < 64 * 128; e += 256) {
        int r = e >> 7, c = e & 127;
        int p = r >> 4;
        float qv = g_Q [(size_t)(b * Nn + p0 + p) * DM + c];
        float kv = g_Kf[(size_t)(b * Nn + s_idx[r]) * DM + c];
        bufA[r * 129 + c] = qv - kv + bufE[r * 129 + c];
    }
    __syncthreads();

    // stage 4/5: gamma MLP
    gemm_tile<16, 129, 129, true >(bufA, Wg1, bg1, bufC, tid, bufW);
    gemm_tile<16, 129, 129, false>(bufC, Wg2, bg2, bufA, tid, bufW);
    __syncthreads();

    // stage 6: softmax over K + weighted sum with (v + pos_enc)
    const float inv_s = 0.08838834764831845f;  // 1/sqrt(128)
    for (int e = tid; e < 4 * 128; e += 256) {
        int p = e >> 7, c = e & 127;
        float mx = -3.4e38f;
        #pragma unroll
        for (int k = 0; k < KK; k++)
            mx = fmaxf(mx, bufA[(p * 16 + k) * 129 + c]);
        float sum = 0.f, acc = 0.f;
        #pragma unroll
        for (int k = 0; k < KK; k++) {
            int r = p * 16 + k;
            float ev = __expf((bufA[r * 129 + c] - mx) * inv_s);
            sum += ev;
            float vv = g_Vf[(size_t)(b * Nn + s_idx[r]) * DM + c] + bufE[r * 129 + c];
            acc = fmaf(ev, vv, acc);
        }
        bufC[p * 129 + c] = acc / sum;
    }
    __syncthreads();

    // stage 7: out = res @ Wo + bo + features
    {
        int p = tid >> 6, j = tid & 63;
        float acc = bo[j];
        #pragma unroll 4
        for (int c = 0; c < 128; c++)
            acc = fmaf(bufC[p * 129 + c], Wo[(size_t)c * DP + j], acc);
        int gp = b * Nn + p0 + p;
        out[(size_t)gp * DP + j] = acc + features[(size_t)gp * DP + j];
    }
}

// ============================================================
extern "C" void kernel_launch(void* const* d_in, const int* in_sizes, int n_in,
                              void* d_out, int out_size)
{
    (void)in_sizes; (void)n_in; (void)out_size;
    const float* xyz      = (const float*)d_in[0];
    const float* features = (const float*)d_in[1];
    const float* Wd1 = (const float*)d_in[2];
    const float* bd1 = (const float*)d_in[3];
    const float* Wd2 = (const float*)d_in[4];
    const float* bd2 = (const float*)d_in[5];
    const float* Wf1 = (const float*)d_in[6];
    const float* bf1 = (const float*)d_in[7];
    const float* Wq  = (const float*)d_in[8];
    const float* Wk  = (const float*)d_in[9];
    const float* Wv  = (const float*)d_in[10];
    const float* Wg1 = (const float*)d_in[11];
    const float* bg1 = (const float*)d_in[12];
    const float* Wg2 = (const float*)d_in[13];
    const float* bg2 = (const float*)d_in[14];
    const float* Wo  = (const float*)d_in[15];
    const float* bo  = (const float*)d_in[16];
    float* out = (float*)d_out;

    knn_kernel<<<dim3(Bb, Nn / 32), 256>>>(xyz);

    size_t sh_fqkv = (64 * 65 + 64 * 129 + 2048) * sizeof(float);
    cudaFuncSetAttribute(fqkv_kernel,
                         cudaFuncAttributeMaxDynamicSharedMemorySize, (int)sh_fqkv);
    fqkv_kernel<<<BN / 64, 256, sh_fqkv>>>(features, Wf1, bf1, Wq, Wk, Wv);

    size_t sh_main = (3 * 64 * 129 + 2048) * sizeof(float);
    cudaFuncSetAttribute(main_kernel,
                         cudaFuncAttributeMaxDynamicSharedMemorySize, (int)sh_main);
    main_kernel<<<BN / 4, 256, sh_main>>>(xyz, features,
                                          Wd1, bd1, Wd2, bd2,
                                          Wg1, bg1, Wg2, bg2,
                                          Wo, bo, out);
}

// round 6
// speedup vs baseline: 3.3845x; 1.3756x over previous
#include <cuda_runtime.h>
#include <cuda_bf16.h>
#include <cstdint>

#define Bb 4
#define Nn 4096
#define KK 16
#define DP 64
#define DM 128
#define BN (Bb*Nn)

// ---- scratch (device globals: allocation-free) ----
__device__ int   g_knn[BN*KK];
__device__ float g_Q [BN*DM];
__device__ float g_Kf[BN*DM];
__device__ float g_Vf[BN*DM];
// pre-split/transposed/swizzled weight tile images:
// [gemm(3)][half hi/lo][ktile(2)] x (128 rows x 64 bf16) = 12 x 16KB
__device__ __nv_bfloat16 g_Wb[3*2*2*128*64];

// ============================================================
// helpers
// ============================================================
__device__ __forceinline__ uint32_t s2u(const void* p) {
    uint32_t a;
    asm("{ .reg .u64 t; cvta.to.shared.u64 t, %1; cvt.u32.u64 %0, t; }"
        : "=r"(a) : "l"(p));
    return a;
}
__device__ __forceinline__ void cp16(void* dst_smem, const void* src) {
    uint32_t d = s2u(dst_smem);
    asm volatile("cp.async.ca.shared.global [%0], [%1], 16;" :: "r"(d), "l"(src) : "memory");
}
__device__ __forceinline__ void cp_commit() {
    asm volatile("cp.async.commit_group;" ::: "memory");
}
__device__ __forceinline__ void cp_wait0() {
    asm volatile("cp.async.wait_group 0;" ::: "memory");
}
__device__ __forceinline__ uint32_t swz(uint32_t o) { return o ^ ((o >> 3) & 0x70); }

__device__ __forceinline__ void ldm4(uint32_t* a, uint32_t addr) {
    asm volatile("ldmatrix.sync.aligned.m8n8.x4.shared.b16 {%0,%1,%2,%3}, [%4];"
        : "=r"(a[0]), "=r"(a[1]), "=r"(a[2]), "=r"(a[3]) : "r"(addr));
}
__device__ __forceinline__ void ldm2(uint32_t* b, uint32_t addr) {
    asm volatile("ldmatrix.sync.aligned.m8n8.x2.shared.b16 {%0,%1}, [%2];"
        : "=r"(b[0]), "=r"(b[1]) : "r"(addr));
}
__device__ __forceinline__ void mma16816(float* d, const uint32_t* a, const uint32_t* b) {
    asm volatile(
        "mma.sync.aligned.m16n8k16.row.col.f32.bf16.bf16.f32 "
        "{%0,%1,%2,%3},{%4,%5,%6,%7},{%8,%9},{%0,%1,%2,%3};"
        : "+f"(d[0]), "+f"(d[1]), "+f"(d[2]), "+f"(d[3])
        : "r"(a[0]), "r"(a[1]), "r"(a[2]), "r"(a[3]), "r"(b[0]), "r"(b[1]));
}

// ============================================================
// prep: split weights into bf16 hi/lo, transpose to [n][k] and
// bake the SW128 swizzle (B operand images for mma.row.col).
// ============================================================
__global__ void __launch_bounds__(128) prep_w(
    const float* __restrict__ Wd2, const float* __restrict__ Wg1,
    const float* __restrict__ Wg2)
{
    int g  = blockIdx.x >> 1;
    int kt = blockIdx.x & 1;
    const float* W = (g == 0) ? Wd2 : ((g == 1) ? Wg1 : Wg2);
    int n = threadIdx.x;
    char* hi = (char*)(g_Wb + (size_t)((g * 2 + 0) * 2 + kt) * 8192);
    char* lo = (char*)(g_Wb + (size_t)((g * 2 + 1) * 2 + kt) * 8192);
    for (int kk = 0; kk < 64; kk++) {
        float v = W[(size_t)(kt * 64 + kk) * DM + n];
        __nv_bfloat16 h = __float2bfloat16(v);
        __nv_bfloat16 l = __float2bfloat16(v - __bfloat162float(h));
        uint32_t sw = swz(n * 128 + kk * 2);
        *(__nv_bfloat16*)(hi + sw) = h;
        *(__nv_bfloat16*)(lo + sw) = l;
    }
}

// ============================================================
// KNN: float4 (x,y,z,|p|^2) smem; register top-16; warp merge
// ============================================================
__global__ void __launch_bounds__(256) knn_kernel(const float* __restrict__ xyz)
{
    extern __shared__ float4 pts[];
    int b = blockIdx.x;
    const float* base = xyz + (size_t)b * Nn * 3;
    for (int j = threadIdx.x; j < Nn; j += blockDim.x) {
        float x = base[j * 3 + 0], y = base[j * 3 + 1], z = base[j * 3 + 2];
        float sq = fmaf(z, z, fmaf(y, y, x * x));
        pts[j] = make_float4(x, y, z, sq);
    }
    __syncthreads();

    int warp = threadIdx.x >> 5, lane = threadIdx.x & 31;
    int q0 = blockIdx.y * 32 + warp * 4;

    for (int qi = 0; qi < 4; qi++) {
        int q = q0 + qi;
        float4 qp = pts[q];
        float qx = qp.x, qy = qp.y, qz = qp.z, qsq = qp.w;

        float bd[KK]; int bi[KK];
        #pragma unroll
        for (int i = 0; i < KK; i++) { bd[i] = 3.4e38f; bi[i] = -1; }

        for (int m = lane; m < Nn; m += 32) {
            float4 c = pts[m];
            float dot = fmaf(qz, c.z, fmaf(qy, c.y, qx * c.x));
            float d2  = (qsq + c.w) - 2.0f * dot;
            if (d2 < bd[KK - 1]) {
                bd[KK - 1] = d2; bi[KK - 1] = m;
                #pragma unroll
                for (int i = KK - 1; i > 0; i--) {
                    bool sw = bd[i] < bd[i - 1];
                    float td = bd[i - 1]; int ti = bi[i - 1];
                    if (sw) {
                        bd[i - 1] = bd[i]; bi[i - 1] = bi[i];
                        bd[i] = td;        bi[i] = ti;
                    }
                }
            }
        }

        int keep = 0;
        #pragma unroll 1
        for (int r = 0; r < KK; r++) {
            float d = bd[0];
            float mn = d;
            #pragma unroll
            for (int off = 16; off; off >>= 1)
                mn = fminf(mn, __shfl_xor_sync(0xffffffffu, mn, off));
            unsigned msk = __ballot_sync(0xffffffffu, d == mn);
            int owner = __ffs(msk) - 1;
            int widx  = __shfl_sync(0xffffffffu, bi[0], owner);
            if (lane == owner) {
                #pragma unroll
                for (int i = 0; i < KK - 1; i++) { bd[i] = bd[i + 1]; bi[i] = bi[i + 1]; }
                bd[KK - 1] = 3.4e38f;
            }
            if (lane == r) keep = widx;
        }
        if (lane < KK) g_knn[((size_t)b * Nn + q) * KK + lane] = keep;
    }
}

// ============================================================
// fqkv: staged SIMT projections
// ============================================================
template<int NCH, int ASTR, int OSTR, bool RELU>
__device__ __forceinline__ void gemm_tile(
    const float* __restrict__ As, const float* __restrict__ W,
    const float* __restrict__ bias, float* __restrict__ Out,
    int tid, float* __restrict__ Wbuf)
{
    int r0 = (tid >> 4) * 4;
    int c0 = (tid & 15) * 8;
    float acc[4][8];
    #pragma unroll
    for (int i = 0; i < 4; i++)
        #pragma unroll
        for (int j = 0; j < 8; j++) acc[i][j] = 0.f;

    cp16(Wbuf + tid * 4, W + tid * 4);
    cp_commit();

    #pragma unroll 1
    for (int ch = 0; ch < NCH; ch++) {
        const float* cur = Wbuf + (ch & 1) * 1024;
        if (ch + 1 < NCH) {
            cp16(Wbuf + ((ch + 1) & 1) * 1024 + tid * 4,
                 W + (size_t)(ch + 1) * 1024 + tid * 4);
            cp_commit();
            asm volatile("cp.async.wait_group 1;" ::: "memory");
        } else {
            cp_wait0();
        }
        __syncthreads();

        #pragma unroll
        for (int k8 = 0; k8 < 8; k8++) {
            const float* wrow = cur + k8 * 128;
            float4 w0 = *reinterpret_cast<const float4*>(wrow + c0);
            float4 w1 = *reinterpret_cast<const float4*>(wrow + c0 + 4);
            float wv[8] = {w0.x, w0.y, w0.z, w0.w, w1.x, w1.y, w1.z, w1.w};
            int kk = ch * 8 + k8;
            float av[4];
            #pragma unroll
            for (int i = 0; i < 4; i++) av[i] = As[(r0 + i) * ASTR + kk];
            #pragma unroll
            for (int i = 0; i < 4; i++)
                #pragma unroll
                for (int j = 0; j < 8; j++)
                    acc[i][j] = fmaf(av[i], wv[j], acc[i][j]);
        }
        __syncthreads();
    }

    float bv[8];
    #pragma unroll
    for (int j = 0; j < 8; j++) bv[j] = bias ? bias[c0 + j] : 0.f;
    #pragma unroll
    for (int i = 0; i < 4; i++) {
        float v[8];
        #pragma unroll
        for (int j = 0; j < 8; j++) {
            v[j] = acc[i][j] + bv[j];
            if (RELU) v[j] = fmaxf(v[j], 0.f);
        }
        if (OSTR == 128) {
            float4* o = reinterpret_cast<float4*>(Out + (size_t)(r0 + i) * OSTR + c0);
            o[0] = make_float4(v[0], v[1], v[2], v[3]);
            o[1] = make_float4(v[4], v[5], v[6], v[7]);
        } else {
            #pragma unroll
            for (int j = 0; j < 8; j++)
                Out[(r0 + i) * OSTR + c0 + j] = v[j];
        }
    }
}

__global__ void __launch_bounds__(256) fqkv_kernel(
    const float* __restrict__ features,
    const float* __restrict__ Wf1, const float* __restrict__ bf1,
    const float* __restrict__ Wq,  const float* __restrict__ Wk,
    const float* __restrict__ Wv)
{
    extern __shared__ float sm[];
    float* s_x  = sm;
    float* s_f  = sm + 64 * 65;
    float* Wbuf = s_f + 64 * 129;

    int row0 = blockIdx.x * 64;
    int tid  = threadIdx.x;

    for (int e = tid; e < 64 * DP; e += 256) {
        int r = e >> 6, c = e & 63;
        s_x[r * 65 + c] = features[(size_t)(row0 + r) * DP + c];
    }
    __syncthreads();

    gemm_tile<8, 65, 129, false>(s_x, Wf1, bf1, s_f, tid, Wbuf);
    gemm_tile<16, 129, 128, false>(s_f, Wq, nullptr, g_Q  + (size_t)row0 * DM, tid, Wbuf);
    gemm_tile<16, 129, 128, false>(s_f, Wk, nullptr, g_Kf + (size_t)row0 * DM, tid, Wbuf);
    gemm_tile<16, 129, 128, false>(s_f, Wv, nullptr, g_Vf + (size_t)row0 * DM, tid, Wbuf);
}

// ============================================================
// A-tile split-bf16 stores (SW128 layout: [hi-k0][hi-k1][lo-k0][lo-k1])
// ============================================================
__device__ __forceinline__ void store8(char* a_t, int r, int c0, const float* v)
{
    int kt = c0 >> 6;
    uint32_t sw = swz(r * 128 + (c0 & 63) * 2);
    char* hib = a_t + kt * 16384;
    char* lob = a_t + 32768 + kt * 16384;
    uint32_t H[4], L[4];
    #pragma unroll
    for (int i = 0; i < 4; i++) {
        __nv_bfloat162 h = __floats2bfloat162_rn(v[2 * i], v[2 * i + 1]);
        float l0 = v[2 * i]     - __low2float(h);
        float l1 = v[2 * i + 1] - __high2float(h);
        __nv_bfloat162 l = __floats2bfloat162_rn(l0, l1);
        H[i] = *reinterpret_cast<uint32_t*>(&h);
        L[i] = *reinterpret_cast<uint32_t*>(&l);
    }
    *reinterpret_cast<uint4*>(hib + sw) = make_uint4(H[0], H[1], H[2], H[3]);
    *reinterpret_cast<uint4*>(lob + sw) = make_uint4(L[0], L[1], L[2], L[3]);
}
__device__ __forceinline__ void stA(char* a_t, int r, int c, float v)
{
    int kt = c >> 6;
    uint32_t sw = swz(r * 128 + (c & 63) * 2);
    __nv_bfloat16 h = __float2bfloat16(v);
    float l = v - __bfloat162float(h);
    *(__nv_bfloat16*)(a_t + kt * 16384 + sw) = h;
    *(__nv_bfloat16*)(a_t + 32768 + kt * 16384 + sw) = __float2bfloat16(l);
}

// ============================================================
// warp-level split-bf16 GEMM: warp computes rows [m0,m0+32) x
// cols [n0,n0+64) of D[128,128] = A @ W^T, 3 passes.
// ============================================================
__device__ __forceinline__ void run_gemm_mma(
    uint32_t aB, uint32_t wB, int m0, int n0, int lane, float acc[2][8][4])
{
    #pragma unroll
    for (int mi = 0; mi < 2; mi++)
        #pragma unroll
        for (int ni = 0; ni < 8; ni++)
            #pragma unroll
            for (int e = 0; e < 4; e++) acc[mi][ni][e] = 0.f;

    #pragma unroll
    for (int p = 0; p < 3; p++) {
        uint32_t aPB = aB + ((p == 2) ? 32768u : 0u);
        uint32_t wPB = wB + ((p == 1) ? 32768u : 0u);
        #pragma unroll
        for (int kt = 0; kt < 2; kt++) {
            uint32_t aT = aPB + kt * 16384;
            uint32_t wT = wPB + kt * 16384;
            #pragma unroll
            for (int ks = 0; ks < 4; ks++) {
                uint32_t a[2][4];
                #pragma unroll
                for (int mi = 0; mi < 2; mi++) {
                    int row = m0 + mi * 16 + (lane & 15);
                    int kb  = ks * 32 + ((lane >> 4) << 4);
                    ldm4(a[mi], aT + swz(row * 128 + kb));
                }
                #pragma unroll
                for (int ni = 0; ni < 8; ni++) {
                    int nrow = n0 + ni * 8 + (lane & 7);
                    int kb2  = ks * 32 + (((lane >> 3) & 1) << 4);
                    uint32_t b[2];
                    ldm2(b, wT + swz(nrow * 128 + kb2));
                    mma16816(acc[0][ni], a[0], b);
                    mma16816(acc[1][ni], a[1], b);
                }
            }
        }
    }
}

// ============================================================
// main kernel: 8 points (128 rows) / block, HMMA GEMMs
// ============================================================
__global__ void __launch_bounds__(256, 1) main_kernel(
    const float* __restrict__ xyz,  const float* __restrict__ features,
    const float* __restrict__ Wd1,  const float* __restrict__ bd1,
    const float* __restrict__ bd2,
    const float* __restrict__ bg1,  const float* __restrict__ bg2,
    const float* __restrict__ Wo,   const float* __restrict__ bo,
    float* __restrict__ out)
{
    extern __shared__ char dsm[];
    uint32_t dbase = s2u(dsm);
    uint32_t pad = (1024u - (dbase & 1023u)) & 1023u;
    char*  a_t = dsm + pad;                    // 4 x 16KB (hi0,hi1,lo0,lo1)
    char*  w_t = a_t + 65536;                  // 4 x 16KB
    float* s_E = (float*)(w_t + 65536);        // 128*129 fp32

    __shared__ float s_wd1[3 * DM], s_bd1[DM], s_bd2[DM], s_bg1[DM], s_bg2[DM], s_bo[DP];
    __shared__ float s_res[8 * 129];
    __shared__ int   s_gi[128];

    const int tid  = threadIdx.x;
    const int wid  = tid >> 5;
    const int lane = tid & 31;
    const int blk  = blockIdx.x;
    const int m0   = (wid & 3) * 32;     // warp row range
    const int n0   = (wid >> 2) * 64;    // warp col half

    // stage small weights/biases
    for (int i = tid; i < 3 * DM; i += 256) s_wd1[i] = Wd1[i];
    if (tid < DM) {
        s_bd1[tid] = bd1[tid]; s_bd2[tid] = bd2[tid];
        s_bg1[tid] = bg1[tid]; s_bg2[tid] = bg2[tid];
    }
    if (tid >= DM && tid < DM + DP) s_bo[tid - DM] = bo[tid - DM];

    // W tiles for GEMM 0
    {
        const char* src = (const char*)g_Wb;
        for (int i = tid; i < 4096; i += 256)
            cp16(w_t + i * 16, src + (size_t)i * 16);
        cp_commit();
    }

    // neighbor indices (thread = row for tid < 128)
    if (tid < 128) {
        int gp = blk * 8 + (tid >> 4);
        int bb = gp >> 12;
        int idx = g_knn[(size_t)gp * KK + (tid & 15)];
        s_gi[tid] = bb * Nn + idx;
    }
    __syncthreads();

    // stage 1: H = relu(rel @ Wd1 + bd1) -> A tiles (hi/lo)
    {
        int r    = tid & 127;
        int half = tid >> 7;
        int gp   = blk * 8 + (r >> 4);
        int gi   = s_gi[r];
        float rx = xyz[(size_t)gp * 3 + 0] - xyz[(size_t)gi * 3 + 0];
        float ry = xyz[(size_t)gp * 3 + 1] - xyz[(size_t)gi * 3 + 1];
        float rz = xyz[(size_t)gp * 3 + 2] - xyz[(size_t)gi * 3 + 2];
        #pragma unroll 2
        for (int c8 = 0; c8 < 64; c8 += 8) {
            int c0 = half * 64 + c8;
            float v[8];
            #pragma unroll
            for (int j = 0; j < 8; j++) {
                int c = c0 + j;
                float h = fmaf(rx, s_wd1[c], fmaf(ry, s_wd1[DM + c],
                           fmaf(rz, s_wd1[2 * DM + c], s_bd1[c])));
                v[j] = fmaxf(h, 0.f);
            }
            store8(a_t, r, c0, v);
        }
    }

    cp_wait0();
    __syncthreads();

    uint32_t aB = s2u(a_t);
    uint32_t wB = s2u(w_t);
    float acc[2][8][4];

    // ---------------- GEMM 0: pos_enc ----------------
    run_gemm_mma(aB, wB, m0, n0, lane, acc);
    __syncthreads();

    // prefetch W for GEMM 1
    {
        const char* src = (const char*)g_Wb + 65536;
        for (int i = tid; i < 4096; i += 256)
            cp16(w_t + i * 16, src + (size_t)i * 16);
        cp_commit();
    }

    // epilogue 0: E = D + bd2 -> s_E ; A = q - k + E -> tiles
    {
        const int gpb = blk * 8;
        #pragma unroll
        for (int mi = 0; mi < 2; mi++) {
            int r0 = m0 + mi * 16 + (lane >> 2);
            int r1 = r0 + 8;
            int gi0 = s_gi[r0], gi1 = s_gi[r1];
            int pt  = (m0 >> 4) + mi;
            const float* qrow = g_Q + (size_t)(gpb + pt) * DM;
            #pragma unroll
            for (int ni = 0; ni < 8; ni++) {
                int c = n0 + ni * 8 + 2 * (lane & 3);
                float q0 = qrow[c], q1 = qrow[c + 1];
                float E00 = acc[mi][ni][0] + s_bd2[c];
                float E01 = acc[mi][ni][1] + s_bd2[c + 1];
                float E10 = acc[mi][ni][2] + s_bd2[c];
                float E11 = acc[mi][ni][3] + s_bd2[c + 1];
                s_E[r0 * 129 + c]     = E00;
                s_E[r0 * 129 + c + 1] = E01;
                s_E[r1 * 129 + c]     = E10;
                s_E[r1 * 129 + c + 1] = E11;
                stA(a_t, r0, c,     q0 - g_Kf[(size_t)gi0 * DM + c]     + E00);
                stA(a_t, r0, c + 1, q1 - g_Kf[(size_t)gi0 * DM + c + 1] + E01);
                stA(a_t, r1, c,     q0 - g_Kf[(size_t)gi1 * DM + c]     + E10);
                stA(a_t, r1, c + 1, q1 - g_Kf[(size_t)gi1 * DM + c + 1] + E11);
            }
        }
    }
    cp_wait0();
    __syncthreads();

    // ---------------- GEMM 1: gamma layer 1 ----------------
    run_gemm_mma(aB, wB, m0, n0, lane, acc);
    __syncthreads();

    // prefetch W for GEMM 2
    {
        const char* src = (const char*)g_Wb + 131072;
        for (int i = tid; i < 4096; i += 256)
            cp16(w_t + i * 16, src + (size_t)i * 16);
        cp_commit();
    }

    // epilogue 1: G = relu(D + bg1) -> tiles
    {
        #pragma unroll
        for (int mi = 0; mi < 2; mi++) {
            int r0 = m0 + mi * 16 + (lane >> 2);
            int r1 = r0 + 8;
            #pragma unroll
            for (int ni = 0; ni < 8; ni++) {
                int c = n0 + ni * 8 + 2 * (lane & 3);
                stA(a_t, r0, c,     fmaxf(acc[mi][ni][0] + s_bg1[c],     0.f));
                stA(a_t, r0, c + 1, fmaxf(acc[mi][ni][1] + s_bg1[c + 1], 0.f));
                stA(a_t, r1, c,     fmaxf(acc[mi][ni][2] + s_bg1[c],     0.f));
                stA(a_t, r1, c + 1, fmaxf(acc[mi][ni][3] + s_bg1[c + 1], 0.f));
            }
        }
    }
    cp_wait0();
    __syncthreads();

    // ---------------- GEMM 2: gamma layer 2 ----------------
    run_gemm_mma(aB, wB, m0, n0, lane, acc);
    __syncthreads();

    // epilogue 2: softmax over the 16 k-rows of each point + weighted sum
    {
        const float inv_s = 0.08838834764831845f;   // 1/sqrt(128)
        #pragma unroll
        for (int mi = 0; mi < 2; mi++) {
            int r0 = m0 + mi * 16 + (lane >> 2);
            int r1 = r0 + 8;
            int gi0 = s_gi[r0], gi1 = s_gi[r1];
            int pt  = (m0 >> 4) + mi;
            #pragma unroll
            for (int ni = 0; ni < 8; ni++) {
                int c = n0 + ni * 8 + 2 * (lane & 3);
                float l0 = acc[mi][ni][0] + s_bg2[c];       // (r0, c)
                float l1 = acc[mi][ni][1] + s_bg2[c + 1];   // (r0, c+1)
                float l2 = acc[mi][ni][2] + s_bg2[c];       // (r1, c)
                float l3 = acc[mi][ni][3] + s_bg2[c + 1];   // (r1, c+1)
                float mA = fmaxf(l0, l2), mB = fmaxf(l1, l3);
                #pragma unroll
                for (int off = 4; off <= 16; off <<= 1) {
                    mA = fmaxf(mA, __shfl_xor_sync(0xffffffffu, mA, off));
                    mB = fmaxf(mB, __shfl_xor_sync(0xffffffffu, mB, off));
                }
                float e0 = __expf((l0 - mA) * inv_s);
                float e2 = __expf((l2 - mA) * inv_s);
                float e1 = __expf((l1 - mB) * inv_s);
                float e3 = __expf((l3 - mB) * inv_s);
                float vE0 = g_Vf[(size_t)gi0 * DM + c]     + s_E[r0 * 129 + c];
                float vE1 = g_Vf[(size_t)gi0 * DM + c + 1] + s_E[r0 * 129 + c + 1];
                float vE2 = g_Vf[(size_t)gi1 * DM + c]     + s_E[r1 * 129 + c];
                float vE3 = g_Vf[(size_t)gi1 * DM + c + 1] + s_E[r1 * 129 + c + 1];
                float sA = e0 + e2,                sB = e1 + e3;
                float nA = fmaf(e0, vE0, e2 * vE2), nB = fmaf(e1, vE1, e3 * vE3);
                #pragma unroll
                for (int off = 4; off <= 16; off <<= 1) {
                    sA += __shfl_xor_sync(0xffffffffu, sA, off);
                    sB += __shfl_xor_sync(0xffffffffu, sB, off);
                    nA += __shfl_xor_sync(0xffffffffu, nA, off);
                    nB += __shfl_xor_sync(0xffffffffu, nB, off);
                }
                if ((lane >> 2) == 0) {
                    s_res[pt * 129 + c]     = nA / sA;
                    s_res[pt * 129 + c + 1] = nB / sB;
                }
            }
        }
    }
    __syncthreads();

    // output: out = res @ Wo + bo + features   [8,64]
    for (int oi = tid; oi < 8 * DP; oi += 256) {
        int pp = oi >> 6, j = oi & 63;
        float acc2 = s_bo[j];
        #pragma unroll 4
        for (int c = 0; c < DM; c++)
            acc2 = fmaf(s_res[pp * 129 + c], Wo[(size_t)c * DP + j], acc2);
        int go = blk * 8 + pp;
        out[(size_t)go * DP + j] = acc2 + features[(size_t)go * DP + j];
    }
}

// ============================================================
extern "C" void kernel_launch(void* const* d_in, const int* in_sizes, int n_in,
                              void* d_out, int out_size)
{
    (void)in_sizes; (void)n_in; (void)out_size;
    const float* xyz      = (const float*)d_in[0];
    const float* features = (const float*)d_in[1];
    const float* Wd1 = (const float*)d_in[2];
    const float* bd1 = (const float*)d_in[3];
    const float* Wd2 = (const float*)d_in[4];
    const float* bd2 = (const float*)d_in[5];
    const float* Wf1 = (const float*)d_in[6];
    const float* bf1 = (const float*)d_in[7];
    const float* Wq  = (const float*)d_in[8];
    const float* Wk  = (const float*)d_in[9];
    const float* Wv  = (const float*)d_in[10];
    const float* Wg1 = (const float*)d_in[11];
    const float* bg1 = (const float*)d_in[12];
    const float* Wg2 = (const float*)d_in[13];
    const float* bg2 = (const float*)d_in[14];
    const float* Wo  = (const float*)d_in[15];
    const float* bo  = (const float*)d_in[16];
    float* out = (float*)d_out;

    prep_w<<<6, 128>>>(Wd2, Wg1, Wg2);

    size_t sh_knn = (size_t)Nn * sizeof(float4);
    cudaFuncSetAttribute(knn_kernel,
                         cudaFuncAttributeMaxDynamicSharedMemorySize, (int)sh_knn);
    knn_kernel<<<dim3(Bb, Nn / 32), 256, sh_knn>>>(xyz);

    size_t sh_fqkv = (64 * 65 + 64 * 129 + 2048) * sizeof(float);
    cudaFuncSetAttribute(fqkv_kernel,
                         cudaFuncAttributeMaxDynamicSharedMemorySize, (int)sh_fqkv);
    fqkv_kernel<<<BN / 64, 256, sh_fqkv>>>(features, Wf1, bf1, Wq, Wk, Wv);

    size_t sh_main = 1024 + 65536 + 65536 + 128 * 129 * sizeof(float);
    cudaFuncSetAttribute(main_kernel,
                         cudaFuncAttributeMaxDynamicSharedMemorySize, (int)sh_main);
    main_kernel<<<BN / 8, 256, sh_main>>>(xyz, features,
                                          Wd1, bd1, bd2, bg1, bg2,
                                          Wo, bo, out);
}

// round 8
// speedup vs baseline: 3.4172x; 1.0097x over previous
#include <cuda_runtime.h>
#include <cuda_bf16.h>
#include <cstdint>

#define Bb 4
#define Nn 4096
#define KK 16
#define DP 64
#define DM 128
#define BN (Bb*Nn)

// ---- scratch (device globals: allocation-free) ----
__device__ int   g_knn[BN*KK];
__device__ float g_Q [BN*DM];
__device__ float g_Kf[BN*DM];
__device__ float g_Vf[BN*DM];
// pre-split/transposed/swizzled weight tile images:
// [gemm(3)][half hi/lo][ktile(2)] x (128 rows x 64 bf16) = 12 x 16KB
__device__ __nv_bfloat16 g_Wb[3*2*2*128*64];

// ============================================================
// helpers
// ============================================================
__device__ __forceinline__ uint32_t s2u(const void* p) {
    uint32_t a;
    asm("{ .reg .u64 t; cvta.to.shared.u64 t, %1; cvt.u32.u64 %0, t; }"
        : "=r"(a) : "l"(p));
    return a;
}
__device__ __forceinline__ void cp16(void* dst_smem, const void* src) {
    uint32_t d = s2u(dst_smem);
    asm volatile("cp.async.ca.shared.global [%0], [%1], 16;" :: "r"(d), "l"(src) : "memory");
}
__device__ __forceinline__ void cp_commit() {
    asm volatile("cp.async.commit_group;" ::: "memory");
}
__device__ __forceinline__ void cp_wait0() {
    asm volatile("cp.async.wait_group 0;" ::: "memory");
}
__device__ __forceinline__ uint32_t swz(uint32_t o) { return o ^ ((o >> 3) & 0x70); }

__device__ __forceinline__ void ldm4(uint32_t* a, uint32_t addr) {
    asm volatile("ldmatrix.sync.aligned.m8n8.x4.shared.b16 {%0,%1,%2,%3}, [%4];"
        : "=r"(a[0]), "=r"(a[1]), "=r"(a[2]), "=r"(a[3]) : "r"(addr));
}
__device__ __forceinline__ void ldm2(uint32_t* b, uint32_t addr) {
    asm volatile("ldmatrix.sync.aligned.m8n8.x2.shared.b16 {%0,%1}, [%2];"
        : "=r"(b[0]), "=r"(b[1]) : "r"(addr));
}
__device__ __forceinline__ void mma16816(float* d, const uint32_t* a, const uint32_t* b) {
    asm volatile(
        "mma.sync.aligned.m16n8k16.row.col.f32.bf16.bf16.f32 "
        "{%0,%1,%2,%3},{%4,%5,%6,%7},{%8,%9},{%0,%1,%2,%3};"
        : "+f"(d[0]), "+f"(d[1]), "+f"(d[2]), "+f"(d[3])
        : "r"(a[0]), "r"(a[1]), "r"(a[2]), "r"(a[3]), "r"(b[0]), "r"(b[1]));
}

// ============================================================
// prep: split weights into bf16 hi/lo, transpose to [n][k] and
// bake the SW128 swizzle (B operand images for mma.row.col).
// ============================================================
__global__ void __launch_bounds__(128) prep_w(
    const float* __restrict__ Wd2, const float* __restrict__ Wg1,
    const float* __restrict__ Wg2)
{
    int g  = blockIdx.x >> 1;
    int kt = blockIdx.x & 1;
    const float* W = (g == 0) ? Wd2 : ((g == 1) ? Wg1 : Wg2);
    int n = threadIdx.x;
    char* hi = (char*)(g_Wb + (size_t)((g * 2 + 0) * 2 + kt) * 8192);
    char* lo = (char*)(g_Wb + (size_t)((g * 2 + 1) * 2 + kt) * 8192);
    for (int kk = 0; kk < 64; kk++) {
        float v = W[(size_t)(kt * 64 + kk) * DM + n];
        __nv_bfloat16 h = __float2bfloat16(v);
        __nv_bfloat16 l = __float2bfloat16(v - __bfloat162float(h));
        uint32_t sw = swz(n * 128 + kk * 2);
        *(__nv_bfloat16*)(hi + sw) = h;
        *(__nv_bfloat16*)(lo + sw) = l;
    }
}

// ============================================================
// KNN: float4 (x,y,z,|p|^2) smem; register top-16; warp merge
// ============================================================
__global__ void __launch_bounds__(256) knn_kernel(const float* __restrict__ xyz)
{
    extern __shared__ float4 pts[];
    int b = blockIdx.x;
    const float* base = xyz + (size_t)b * Nn * 3;
    for (int j = threadIdx.x; j < Nn; j += blockDim.x) {
        float x = base[j * 3 + 0], y = base[j * 3 + 1], z = base[j * 3 + 2];
        float sq = fmaf(z, z, fmaf(y, y, x * x));
        pts[j] = make_float4(x, y, z, sq);
    }
    __syncthreads();

    int warp = threadIdx.x >> 5, lane = threadIdx.x & 31;
    int q0 = blockIdx.y * 32 + warp * 4;

    for (int qi = 0; qi < 4; qi++) {
        int q = q0 + qi;
        float4 qp = pts[q];
        float qx = qp.x, qy = qp.y, qz = qp.z, qsq = qp.w;

        float bd[KK]; int bi[KK];
        #pragma unroll
        for (int i = 0; i < KK; i++) { bd[i] = 3.4e38f; bi[i] = -1; }

        for (int m = lane; m < Nn; m += 32) {
            float4 c = pts[m];
            float dot = fmaf(qz, c.z, fmaf(qy, c.y, qx * c.x));
            float d2  = (qsq + c.w) - 2.0f * dot;
            if (d2 < bd[KK - 1]) {
                bd[KK - 1] = d2; bi[KK - 1] = m;
                #pragma unroll
                for (int i = KK - 1; i > 0; i--) {
                    bool sw = bd[i] < bd[i - 1];
                    float td = bd[i - 1]; int ti = bi[i - 1];
                    if (sw) {
                        bd[i - 1] = bd[i]; bi[i - 1] = bi[i];
                        bd[i] = td;        bi[i] = ti;
                    }
                }
            }
        }

        int keep = 0;
        #pragma unroll 1
        for (int r = 0; r < KK; r++) {
            float d = bd[0];
            float mn = d;
            #pragma unroll
            for (int off = 16; off; off >>= 1)
                mn = fminf(mn, __shfl_xor_sync(0xffffffffu, mn, off));
            unsigned msk = __ballot_sync(0xffffffffu, d == mn);
            int owner = __ffs(msk) - 1;
            int widx  = __shfl_sync(0xffffffffu, bi[0], owner);
            if (lane == owner) {
                #pragma unroll
                for (int i = 0; i < KK - 1; i++) { bd[i] = bd[i + 1]; bi[i] = bi[i + 1]; }
                bd[KK - 1] = 3.4e38f;
            }
            if (lane == r) keep = widx;
        }
        if (lane < KK) g_knn[((size_t)b * Nn + q) * KK + lane] = keep;
    }
}

// ============================================================
// fqkv: staged SIMT projections
// ============================================================
template<int NCH, int ASTR, int OSTR, bool RELU>
__device__ __forceinline__ void gemm_tile(
    const float* __restrict__ As, const float* __restrict__ W,
    const float* __restrict__ bias, float* __restrict__ Out,
    int tid, float* __restrict__ Wbuf)
{
    int r0 = (tid >> 4) * 4;
    int c0 = (tid & 15) * 8;
    float acc[4][8];
    #pragma unroll
    for (int i = 0; i < 4; i++)
        #pragma unroll
        for (int j = 0; j < 8; j++) acc[i][j] = 0.f;

    cp16(Wbuf + tid * 4, W + tid * 4);
    cp_commit();

    #pragma unroll 1
    for (int ch = 0; ch < NCH; ch++) {
        const float* cur = Wbuf + (ch & 1) * 1024;
        if (ch + 1 < NCH) {
            cp16(Wbuf + ((ch + 1) & 1) * 1024 + tid * 4,
                 W + (size_t)(ch + 1) * 1024 + tid * 4);
            cp_commit();
            asm volatile("cp.async.wait_group 1;" ::: "memory");
        } else {
            cp_wait0();
        }
        __syncthreads();

        #pragma unroll
        for (int k8 = 0; k8 < 8; k8++) {
            const float* wrow = cur + k8 * 128;
            float4 w0 = *reinterpret_cast<const float4*>(wrow + c0);
            float4 w1 = *reinterpret_cast<const float4*>(wrow + c0 + 4);
            float wv[8] = {w0.x, w0.y, w0.z, w0.w, w1.x, w1.y, w1.z, w1.w};
            int kk = ch * 8 + k8;
            float av[4];
            #pragma unroll
            for (int i = 0; i < 4; i++) av[i] = As[(r0 + i) * ASTR + kk];
            #pragma unroll
            for (int i = 0; i < 4; i++)
                #pragma unroll
                for (int j = 0; j < 8; j++)
                    acc[i][j] = fmaf(av[i], wv[j], acc[i][j]);
        }
        __syncthreads();
    }

    float bv[8];
    #pragma unroll
    for (int j = 0; j < 8; j++) bv[j] = bias ? bias[c0 + j] : 0.f;
    #pragma unroll
    for (int i = 0; i < 4; i++) {
        float v[8];
        #pragma unroll
        for (int j = 0; j < 8; j++) {
            v[j] = acc[i][j] + bv[j];
            if (RELU) v[j] = fmaxf(v[j], 0.f);
        }
        if (OSTR == 128) {
            float4* o = reinterpret_cast<float4*>(Out + (size_t)(r0 + i) * OSTR + c0);
            o[0] = make_float4(v[0], v[1], v[2], v[3]);
            o[1] = make_float4(v[4], v[5], v[6], v[7]);
        } else {
            #pragma unroll
            for (int j = 0; j < 8; j++)
                Out[(r0 + i) * OSTR + c0 + j] = v[j];
        }
    }
}

__global__ void __launch_bounds__(256) fqkv_kernel(
    const float* __restrict__ features,
    const float* __restrict__ Wf1, const float* __restrict__ bf1,
    const float* __restrict__ Wq,  const float* __restrict__ Wk,
    const float* __restrict__ Wv)
{
    extern __shared__ float sm[];
    float* s_x  = sm;
    float* s_f  = sm + 64 * 65;
    float* Wbuf = s_f + 64 * 129;

    int row0 = blockIdx.x * 64;
    int tid  = threadIdx.x;

    for (int e = tid; e < 64 * DP; e += 256) {
        int r = e >> 6, c = e & 63;
        s_x[r * 65 + c] = features[(size_t)(row0 + r) * DP + c];
    }
    __syncthreads();

    gemm_tile<8, 65, 129, false>(s_x, Wf1, bf1, s_f, tid, Wbuf);
    gemm_tile<16, 129, 128, false>(s_f, Wq, nullptr, g_Q  + (size_t)row0 * DM, tid, Wbuf);
    gemm_tile<16, 129, 128, false>(s_f, Wk, nullptr, g_Kf + (size_t)row0 * DM, tid, Wbuf);
    gemm_tile<16, 129, 128, false>(s_f, Wv, nullptr, g_Vf + (size_t)row0 * DM, tid, Wbuf);
}

// ============================================================
// A-tile split-bf16 stores (SW128 layout: [hi-k0][hi-k1][lo-k0][lo-k1])
// ============================================================
__device__ __forceinline__ void store8(char* a_t, int r, int c0, const float* v)
{
    int kt = c0 >> 6;
    uint32_t sw = swz(r * 128 + (c0 & 63) * 2);
    char* hib = a_t + kt * 16384;
    char* lob = a_t + 32768 + kt * 16384;
    uint32_t H[4], L[4];
    #pragma unroll
    for (int i = 0; i < 4; i++) {
        __nv_bfloat162 h = __floats2bfloat162_rn(v[2 * i], v[2 * i + 1]);
        float l0 = v[2 * i]     - __low2float(h);
        float l1 = v[2 * i + 1] - __high2float(h);
        __nv_bfloat162 l = __floats2bfloat162_rn(l0, l1);
        H[i] = *reinterpret_cast<uint32_t*>(&h);
        L[i] = *reinterpret_cast<uint32_t*>(&l);
    }
    *reinterpret_cast<uint4*>(hib + sw) = make_uint4(H[0], H[1], H[2], H[3]);
    *reinterpret_cast<uint4*>(lob + sw) = make_uint4(L[0], L[1], L[2], L[3]);
}
__device__ __forceinline__ void stA(char* a_t, int r, int c, float v)
{
    int kt = c >> 6;
    uint32_t sw = swz(r * 128 + (c & 63) * 2);
    __nv_bfloat16 h = __float2bfloat16(v);
    float l = v - __bfloat162float(h);
    *(__nv_bfloat16*)(a_t + kt * 16384 + sw) = h;
    *(__nv_bfloat16*)(a_t + 32768 + kt * 16384 + sw) = __float2bfloat16(l);
}

// ============================================================
// warp-level split-bf16 GEMM: warp computes rows [m0,m0+16) x
// cols [n0,n0+64) of D[128,128] = A @ W^T, 3 passes.
// ============================================================
__device__ __forceinline__ void run_gemm_mma(
    uint32_t aB, uint32_t wB, int m0, int n0, int lane, float acc[8][4])
{
    #pragma unroll
    for (int ni = 0; ni < 8; ni++)
        #pragma unroll
        for (int e = 0; e < 4; e++) acc[ni][e] = 0.f;

    #pragma unroll
    for (int p = 0; p < 3; p++) {
        uint32_t aPB = aB + ((p == 2) ? 32768u : 0u);
        uint32_t wPB = wB + ((p == 1) ? 32768u : 0u);
        #pragma unroll
        for (int kt = 0; kt < 2; kt++) {
            uint32_t aT = aPB + kt * 16384;
            uint32_t wT = wPB + kt * 16384;
            #pragma unroll
            for (int ks = 0; ks < 4; ks++) {
                uint32_t a[4];
                int row = m0 + (lane & 15);
                int kb  = ks * 32 + ((lane >> 4) << 4);
                ldm4(a, aT + swz(row * 128 + kb));
                #pragma unroll
                for (int ni = 0; ni < 8; ni++) {
                    int nrow = n0 + ni * 8 + (lane & 7);
                    int kb2  = ks * 32 + (((lane >> 3) & 1) << 4);
                    uint32_t b[2];
                    ldm2(b, wT + swz(nrow * 128 + kb2));
                    mma16816(acc[ni], a, b);
                }
            }
        }
    }
}

// ============================================================
// main kernel: 8 points (128 rows) / block, 512 threads,
// HMMA GEMMs, pos_enc E kept in registers.
// ============================================================
__global__ void __launch_bounds__(512, 1) main_kernel(
    const float* __restrict__ xyz,  const float* __restrict__ features,
    const float* __restrict__ Wd1,  const float* __restrict__ bd1,
    const float* __restrict__ bd2,
    const float* __restrict__ bg1,  const float* __restrict__ bg2,
    const float* __restrict__ Wo,   const float* __restrict__ bo,
    float* __restrict__ out)
{
    extern __shared__ char dsm[];
    uint32_t dbase = s2u(dsm);
    uint32_t pad = (1024u - (dbase & 1023u)) & 1023u;
    char*  a_t = dsm + pad;                    // 4 x 16KB (hi0,hi1,lo0,lo1)
    char*  w_t = a_t + 65536;                  // 4 x 16KB

    __shared__ float s_wd1[3 * DM], s_bd1[DM], s_bd2[DM], s_bg1[DM], s_bg2[DM], s_bo[DP];
    __shared__ float s_res[8 * 129];
    __shared__ int   s_gi[128];

    const int tid  = threadIdx.x;
    const int wid  = tid >> 5;
    const int lane = tid & 31;
    const int blk  = blockIdx.x;
    const int m0   = (wid & 7) * 16;     // warp row range (one point)
    const int n0   = (wid >> 3) * 64;    // warp col half

    // stage small weights/biases
    for (int i = tid; i < 3 * DM; i += 512) s_wd1[i] = Wd1[i];
    if (tid < DM) {
        s_bd1[tid] = bd1[tid]; s_bd2[tid] = bd2[tid];
        s_bg1[tid] = bg1[tid]; s_bg2[tid] = bg2[tid];
    }
    if (tid >= DM && tid < DM + DP) s_bo[tid - DM] = bo[tid - DM];

    // W tiles for GEMM 0
    {
        const char* src = (const char*)g_Wb;
        for (int i = tid; i < 4096; i += 512)
            cp16(w_t + i * 16, src + (size_t)i * 16);
        cp_commit();
    }

    // neighbor indices (thread = row for tid < 128)
    if (tid < 128) {
        int gp = blk * 8 + (tid >> 4);
        int bb = gp >> 12;
        int idx = g_knn[(size_t)gp * KK + (tid & 15)];
        s_gi[tid] = bb * Nn + idx;
    }
    __syncthreads();

    // stage 1: H = relu(rel @ Wd1 + bd1) -> A tiles (hi/lo)
    {
        int r  = tid & 127;
        int qq = tid >> 7;                  // 0..3 column quarter
        int gp = blk * 8 + (r >> 4);
        int gi = s_gi[r];
        float rx = xyz[(size_t)gp * 3 + 0] - xyz[(size_t)gi * 3 + 0];
        float ry = xyz[(size_t)gp * 3 + 1] - xyz[(size_t)gi * 3 + 1];
        float rz = xyz[(size_t)gp * 3 + 2] - xyz[(size_t)gi * 3 + 2];
        #pragma unroll
        for (int cg = 0; cg < 4; cg++) {
            int c0 = qq * 32 + cg * 8;
            float v[8];
            #pragma unroll
            for (int j = 0; j < 8; j++) {
                int c = c0 + j;
                float h = fmaf(rx, s_wd1[c], fmaf(ry, s_wd1[DM + c],
                           fmaf(rz, s_wd1[2 * DM + c], s_bd1[c])));
                v[j] = fmaxf(h, 0.f);
            }
            store8(a_t, r, c0, v);
        }
    }

    cp_wait0();
    __syncthreads();

    uint32_t aB = s2u(a_t);
    uint32_t wB = s2u(w_t);
    float acc[8][4];
    float E[8][4];                        // pos_enc fragment (register-resident)

    // ---------------- GEMM 0: pos_enc ----------------
    run_gemm_mma(aB, wB, m0, n0, lane, acc);
    __syncthreads();

    // prefetch W for GEMM 1
    {
        const char* src = (const char*)g_Wb + 65536;
        for (int i = tid; i < 4096; i += 512)
            cp16(w_t + i * 16, src + (size_t)i * 16);
        cp_commit();
    }

    // epilogue 0: E = D + bd2 (registers) ; A = q - k + E -> tiles
    {
        int r0 = m0 + (lane >> 2);
        int r1 = r0 + 8;
        int gi0 = s_gi[r0], gi1 = s_gi[r1];
        int pt  = m0 >> 4;
        const float* qrow = g_Q + (size_t)(blk * 8 + pt) * DM;
        #pragma unroll
        for (int ni = 0; ni < 8; ni++) {
            int c = n0 + ni * 8 + 2 * (lane & 3);
            float q0 = qrow[c], q1 = qrow[c + 1];
            E[ni][0] = acc[ni][0] + s_bd2[c];
            E[ni][1] = acc[ni][1] + s_bd2[c + 1];
            E[ni][2] = acc[ni][2] + s_bd2[c];
            E[ni][3] = acc[ni][3] + s_bd2[c + 1];
            stA(a_t, r0, c,     q0 - g_Kf[(size_t)gi0 * DM + c]     + E[ni][0]);
            stA(a_t, r0, c + 1, q1 - g_Kf[(size_t)gi0 * DM + c + 1] + E[ni][1]);
            stA(a_t, r1, c,     q0 - g_Kf[(size_t)gi1 * DM + c]     + E[ni][2]);
            stA(a_t, r1, c + 1, q1 - g_Kf[(size_t)gi1 * DM + c + 1] + E[ni][3]);
        }
    }
    cp_wait0();
    __syncthreads();

    // ---------------- GEMM 1: gamma layer 1 ----------------
    run_gemm_mma(aB, wB, m0, n0, lane, acc);
    __syncthreads();

    // prefetch W for GEMM 2
    {
        const char* src = (const char*)g_Wb + 131072;
        for (int i = tid; i < 4096; i += 512)
            cp16(w_t + i * 16, src + (size_t)i * 16);
        cp_commit();
    }

    // epilogue 1: G = relu(D + bg1) -> tiles
    {
        int r0 = m0 + (lane >> 2);
        int r1 = r0 + 8;
        #pragma unroll
        for (int ni = 0; ni < 8; ni++) {
            int c = n0 + ni * 8 + 2 * (lane & 3);
            stA(a_t, r0, c,     fmaxf(acc[ni][0] + s_bg1[c],     0.f));
            stA(a_t, r0, c + 1, fmaxf(acc[ni][1] + s_bg1[c + 1], 0.f));
            stA(a_t, r1, c,     fmaxf(acc[ni][2] + s_bg1[c],     0.f));
            stA(a_t, r1, c + 1, fmaxf(acc[ni][3] + s_bg1[c + 1], 0.f));
        }
    }
    cp_wait0();
    __syncthreads();

    // ---------------- GEMM 2: gamma layer 2 ----------------
    run_gemm_mma(aB, wB, m0, n0, lane, acc);
    __syncthreads();

    // epilogue 2: softmax over the 16 k-rows of the warp's point
    {
        const float inv_s = 0.08838834764831845f;   // 1/sqrt(128)
        int r0 = m0 + (lane >> 2);
        int r1 = r0 + 8;
        int gi0 = s_gi[r0], gi1 = s_gi[r1];
        int pt  = m0 >> 4;
        #pragma unroll
        for (int ni = 0; ni < 8; ni++) {
            int c = n0 + ni * 8 + 2 * (lane & 3);
            float l0 = acc[ni][0] + s_bg2[c];       // (r0, c)
            float l1 = acc[ni][1] + s_bg2[c + 1];   // (r0, c+1)
            float l2 = acc[ni][2] + s_bg2[c];       // (r1, c)
            float l3 = acc[ni][3] + s_bg2[c + 1];   // (r1, c+1)
            float mA = fmaxf(l0, l2), mB = fmaxf(l1, l3);
            #pragma unroll
            for (int off = 4; off <= 16; off <<= 1) {
                mA = fmaxf(mA, __shfl_xor_sync(0xffffffffu, mA, off));
                mB = fmaxf(mB, __shfl_xor_sync(0xffffffffu, mB, off));
            }
            float e0 = __expf((l0 - mA) * inv_s);
            float e2 = __expf((l2 - mA) * inv_s);
            float e1 = __expf((l1 - mB) * inv_s);
            float e3 = __expf((l3 - mB) * inv_s);
            float vE0 = g_Vf[(size_t)gi0 * DM + c]     + E[ni][0];
            float vE1 = g_Vf[(size_t)gi0 * DM + c + 1] + E[ni][1];
            float vE2 = g_Vf[(size_t)gi1 * DM + c]     + E[ni][2];
            float vE3 = g_Vf[(size_t)gi1 * DM + c + 1] + E[ni][3];
            float sA = e0 + e2,                sB = e1 + e3;
            float nA = fmaf(e0, vE0, e2 * vE2), nB = fmaf(e1, vE1, e3 * vE3);
            #pragma unroll
            for (int off = 4; off <= 16; off <<= 1) {
                sA += __shfl_xor_sync(0xffffffffu, sA, off);
                sB += __shfl_xor_sync(0xffffffffu, sB, off);
                nA += __shfl_xor_sync(0xffffffffu, nA, off);
                nB += __shfl_xor_sync(0xffffffffu, nB, off);
            }
            if ((lane >> 2) == 0) {
                s_res[pt * 129 + c]     = nA / sA;
                s_res[pt * 129 + c + 1] = nB / sB;
            }
        }
    }
    __syncthreads();

    // output: out = res @ Wo + bo + features   [8,64] (one elem/thread)
    {
        int pp = tid >> 6, j = tid & 63;
        float acc2 = s_bo[j];
        #pragma unroll 4
        for (int c = 0; c < DM; c++)
            acc2 = fmaf(s_res[pp * 129 + c], Wo[(size_t)c * DP + j], acc2);
        int go = blk * 8 + pp;
        out[(size_t)go * DP + j] = acc2 + features[(size_t)go * DP + j];
    }
}

// ============================================================
extern "C" void kernel_launch(void* const* d_in, const int* in_sizes, int n_in,
                              void* d_out, int out_size)
{
    (void)in_sizes; (void)n_in; (void)out_size;
    const float* xyz      = (const float*)d_in[0];
    const float* features = (const float*)d_in[1];
    const float* Wd1 = (const float*)d_in[2];
    const float* bd1 = (const float*)d_in[3];
    const float* Wd2 = (const float*)d_in[4];
    const float* bd2 = (const float*)d_in[5];
    const float* Wf1 = (const float*)d_in[6];
    const float* bf1 = (const float*)d_in[7];
    const float* Wq  = (const float*)d_in[8];
    const float* Wk  = (const float*)d_in[9];
    const float* Wv  = (const float*)d_in[10];
    const float* Wg1 = (const float*)d_in[11];
    const float* bg1 = (const float*)d_in[12];
    const float* Wg2 = (const float*)d_in[13];
    const float* bg2 = (const float*)d_in[14];
    const float* Wo  = (const float*)d_in[15];
    const float* bo  = (const float*)d_in[16];
    float* out = (float*)d_out;

    prep_w<<<6, 128>>>(Wd2, Wg1, Wg2);

    size_t sh_knn = (size_t)Nn * sizeof(float4);
    cudaFuncSetAttribute(knn_kernel,
                         cudaFuncAttributeMaxDynamicSharedMemorySize, (int)sh_knn);
    knn_kernel<<<dim3(Bb, Nn / 32), 256, sh_knn>>>(xyz);

    size_t sh_fqkv = (64 * 65 + 64 * 129 + 2048) * sizeof(float);
    cudaFuncSetAttribute(fqkv_kernel,
                         cudaFuncAttributeMaxDynamicSharedMemorySize, (int)sh_fqkv);
    fqkv_kernel<<<BN / 64, 256, sh_fqkv>>>(features, Wf1, bf1, Wq, Wk, Wv);

    size_t sh_main = 1024 + 65536 + 65536;
    cudaFuncSetAttribute(main_kernel,
                         cudaFuncAttributeMaxDynamicSharedMemorySize, (int)sh_main);
    main_kernel<<<BN / 8, 512, sh_main>>>(xyz, features,
                                          Wd1, bd1, bd2, bg1, bg2,
                                          Wo, bo, out);
}

// round 10
// speedup vs baseline: 3.5997x; 1.0534x over previous
#include <cuda_runtime.h>
#include <cuda_bf16.h>
#include <cstdint>

#define Bb 4
#define Nn 4096
#define KK 16
#define DP 64
#define DM 128
#define BN (Bb*Nn)

// ---- scratch (device globals: allocation-free) ----
__device__ int   g_knn[BN*KK];
__device__ float g_Q [BN*DM];
__device__ float g_Kf[BN*DM];
__device__ float g_Vf[BN*DM];
// pre-split/transposed/swizzled weight tile images:
// [gemm(3)][half hi/lo][ktile(2)] x (128 rows x 64 bf16) = 12 x 16KB
__device__ __nv_bfloat16 g_Wb[3*2*2*128*64];

#define KV_STR 136   // floats per staged K/V row (bank spreading, 16B aligned)

// ============================================================
// helpers
// ============================================================
__device__ __forceinline__ uint32_t s2u(const void* p) {
    uint32_t a;
    asm("{ .reg .u64 t; cvta.to.shared.u64 t, %1; cvt.u32.u64 %0, t; }"
        : "=r"(a) : "l"(p));
    return a;
}
__device__ __forceinline__ void cp16(void* dst_smem, const void* src) {
    uint32_t d = s2u(dst_smem);
    asm volatile("cp.async.ca.shared.global [%0], [%1], 16;" :: "r"(d), "l"(src) : "memory");
}
__device__ __forceinline__ void cp_commit() {
    asm volatile("cp.async.commit_group;" ::: "memory");
}
__device__ __forceinline__ void cp_wait0() {
    asm volatile("cp.async.wait_group 0;" ::: "memory");
}
__device__ __forceinline__ uint32_t swz(uint32_t o) { return o ^ ((o >> 3) & 0x70); }

__device__ __forceinline__ void ldm4(uint32_t* a, uint32_t addr) {
    asm volatile("ldmatrix.sync.aligned.m8n8.x4.shared.b16 {%0,%1,%2,%3}, [%4];"
        : "=r"(a[0]), "=r"(a[1]), "=r"(a[2]), "=r"(a[3]) : "r"(addr));
}
__device__ __forceinline__ void mma16816(float* d, const uint32_t* a, const uint32_t* b) {
    asm volatile(
        "mma.sync.aligned.m16n8k16.row.col.f32.bf16.bf16.f32 "
        "{%0,%1,%2,%3},{%4,%5,%6,%7},{%8,%9},{%0,%1,%2,%3};"
        : "+f"(d[0]), "+f"(d[1]), "+f"(d[2]), "+f"(d[3])
        : "r"(a[0]), "r"(a[1]), "r"(a[2]), "r"(a[3]), "r"(b[0]), "r"(b[1]));
}

// ============================================================
// prep: split weights into bf16 hi/lo, transpose to [n][k] and
// bake the SW128 swizzle (B operand images for mma.row.col).
// ============================================================
__global__ void __launch_bounds__(128) prep_w(
    const float* __restrict__ Wd2, const float* __restrict__ Wg1,
    const float* __restrict__ Wg2)
{
    int g  = blockIdx.x >> 1;
    int kt = blockIdx.x & 1;
    const float* W = (g == 0) ? Wd2 : ((g == 1) ? Wg1 : Wg2);
    int n = threadIdx.x;
    char* hi = (char*)(g_Wb + (size_t)((g * 2 + 0) * 2 + kt) * 8192);
    char* lo = (char*)(g_Wb + (size_t)((g * 2 + 1) * 2 + kt) * 8192);
    for (int kk = 0; kk < 64; kk++) {
        float v = W[(size_t)(kt * 64 + kk) * DM + n];
        __nv_bfloat16 h = __float2bfloat16(v);
        __nv_bfloat16 l = __float2bfloat16(v - __bfloat162float(h));
        uint32_t sw = swz(n * 128 + kk * 2);
        *(__nv_bfloat16*)(hi + sw) = h;
        *(__nv_bfloat16*)(lo + sw) = l;
    }
}

// ============================================================
// KNN: float4 (x,y,z,0.5*|p|^2) smem; select on t = 0.5*csq - dot
// (monotonic transform of d2 for fixed query -> same top-16 set/order)
// ============================================================
__global__ void __launch_bounds__(256) knn_kernel(const float* __restrict__ xyz)
{
    extern __shared__ float4 pts[];
    int b = blockIdx.x;
    const float* base = xyz + (size_t)b * Nn * 3;
    for (int j = threadIdx.x; j < Nn; j += blockDim.x) {
        float x = base[j * 3 + 0], y = base[j * 3 + 1], z = base[j * 3 + 2];
        float sq = fmaf(z, z, fmaf(y, y, x * x));
        pts[j] = make_float4(x, y, z, 0.5f * sq);
    }
    __syncthreads();

    int warp = threadIdx.x >> 5, lane = threadIdx.x & 31;
    int q0 = blockIdx.y * 32 + warp * 4;

    for (int qi = 0; qi < 4; qi++) {
        int q = q0 + qi;
        float4 qp = pts[q];
        float qx = qp.x, qy = qp.y, qz = qp.z;

        float bd[KK]; int bi[KK];
        #pragma unroll
        for (int i = 0; i < KK; i++) { bd[i] = 3.4e38f; bi[i] = -1; }

        #pragma unroll 4
        for (int m = lane; m < Nn; m += 32) {
            float4 c = pts[m];
            float s = fmaf(qy, c.y, qx * c.x);
            float t = c.w - fmaf(qz, c.z, s);      // 0.5*d2 - 0.5*qsq
            if (t < bd[KK - 1]) {
                bd[KK - 1] = t; bi[KK - 1] = m;
                #pragma unroll
                for (int i = KK - 1; i > 0; i--) {
                    bool sw = bd[i] < bd[i - 1];
                    float td = bd[i - 1]; int ti = bi[i - 1];
                    if (sw) {
                        bd[i - 1] = bd[i]; bi[i - 1] = bi[i];
                        bd[i] = td;        bi[i] = ti;
                    }
                }
            }
        }

        int keep = 0;
        #pragma unroll 1
        for (int r = 0; r < KK; r++) {
            float d = bd[0];
            float mn = d;
            #pragma unroll
            for (int off = 16; off; off >>= 1)
                mn = fminf(mn, __shfl_xor_sync(0xffffffffu, mn, off));
            unsigned msk = __ballot_sync(0xffffffffu, d == mn);
            int owner = __ffs(msk) - 1;
            int widx  = __shfl_sync(0xffffffffu, bi[0], owner);
            if (lane == owner) {
                #pragma unroll
                for (int i = 0; i < KK - 1; i++) { bd[i] = bd[i + 1]; bi[i] = bi[i + 1]; }
                bd[KK - 1] = 3.4e38f;
            }
            if (lane == r) keep = widx;
        }
        if (lane < KK) g_knn[((size_t)b * Nn + q) * KK + lane] = keep;
    }
}

// ============================================================
// fqkv: staged SIMT projections
// ============================================================
template<int NCH, int ASTR, int OSTR, bool RELU>
__device__ __forceinline__ void gemm_tile(
    const float* __restrict__ As, const float* __restrict__ W,
    const float* __restrict__ bias, float* __restrict__ Out,
    int tid, float* __restrict__ Wbuf)
{
    int r0 = (tid >> 4) * 4;
    int c0 = (tid & 15) * 8;
    float acc[4][8];
    #pragma unroll
    for (int i = 0; i < 4; i++)
        #pragma unroll
        for (int j = 0; j < 8; j++) acc[i][j] = 0.f;

    cp16(Wbuf + tid * 4, W + tid * 4);
    cp_commit();

    #pragma unroll 1
    for (int ch = 0; ch < NCH; ch++) {
        const float* cur = Wbuf + (ch & 1) * 1024;
        if (ch + 1 < NCH) {
            cp16(Wbuf + ((ch + 1) & 1) * 1024 + tid * 4,
                 W + (size_t)(ch + 1) * 1024 + tid * 4);
            cp_commit();
            asm volatile("cp.async.wait_group 1;" ::: "memory");
        } else {
            cp_wait0();
        }
        __syncthreads();

        #pragma unroll
        for (int k8 = 0; k8 < 8; k8++) {
            const float* wrow = cur + k8 * 128;
            float4 w0 = *reinterpret_cast<const float4*>(wrow + c0);
            float4 w1 = *reinterpret_cast<const float4*>(wrow + c0 + 4);
            float wv[8] = {w0.x, w0.y, w0.z, w0.w, w1.x, w1.y, w1.z, w1.w};
            int kk = ch * 8 + k8;
            float av[4];
            #pragma unroll
            for (int i = 0; i < 4; i++) av[i] = As[(r0 + i) * ASTR + kk];
            #pragma unroll
            for (int i = 0; i < 4; i++)
                #pragma unroll
                for (int j = 0; j < 8; j++)
                    acc[i][j] = fmaf(av[i], wv[j], acc[i][j]);
        }
        __syncthreads();
    }

    float bv[8];
    #pragma unroll
    for (int j = 0; j < 8; j++) bv[j] = bias ? bias[c0 + j] : 0.f;
    #pragma unroll
    for (int i = 0; i < 4; i++) {
        float v[8];
        #pragma unroll
        for (int j = 0; j < 8; j++) {
            v[j] = acc[i][j] + bv[j];
            if (RELU) v[j] = fmaxf(v[j], 0.f);
        }
        if (OSTR == 128) {
            float4* o = reinterpret_cast<float4*>(Out + (size_t)(r0 + i) * OSTR + c0);
            o[0] = make_float4(v[0], v[1], v[2], v[3]);
            o[1] = make_float4(v[4], v[5], v[6], v[7]);
        } else {
            #pragma unroll
            for (int j = 0; j < 8; j++)
                Out[(r0 + i) * OSTR + c0 + j] = v[j];
        }
    }
}

__global__ void __launch_bounds__(256) fqkv_kernel(
    const float* __restrict__ features,
    const float* __restrict__ Wf1, const float* __restrict__ bf1,
    const float* __restrict__ Wq,  const float* __restrict__ Wk,
    const float* __restrict__ Wv)
{
    extern __shared__ float sm[];
    float* s_x  = sm;
    float* s_f  = sm + 64 * 65;
    float* Wbuf = s_f + 64 * 129;

    int row0 = blockIdx.x * 64;
    int tid  = threadIdx.x;

    for (int e = tid; e < 64 * DP; e += 256) {
        int r = e >> 6, c = e & 63;
        s_x[r * 65 + c] = features[(size_t)(row0 + r) * DP + c];
    }
    __syncthreads();

    gemm_tile<8, 65, 129, false>(s_x, Wf1, bf1, s_f, tid, Wbuf);
    gemm_tile<16, 129, 128, false>(s_f, Wq, nullptr, g_Q  + (size_t)row0 * DM, tid, Wbuf);
    gemm_tile<16, 129, 128, false>(s_f, Wk, nullptr, g_Kf + (size_t)row0 * DM, tid, Wbuf);
    gemm_tile<16, 129, 128, false>(s_f, Wv, nullptr, g_Vf + (size_t)row0 * DM, tid, Wbuf);
}

// ============================================================
// A-tile split-bf16 stores (SW128 layout: [hi-k0][hi-k1][lo-k0][lo-k1])
// ============================================================
__device__ __forceinline__ void store8(char* a_t, int r, int c0, const float* v)
{
    int kt = c0 >> 6;
    uint32_t sw = swz(r * 128 + (c0 & 63) * 2);
    char* hib = a_t + kt * 16384;
    char* lob = a_t + 32768 + kt * 16384;
    uint32_t H[4], L[4];
    #pragma unroll
    for (int i = 0; i < 4; i++) {
        __nv_bfloat162 h = __floats2bfloat162_rn(v[2 * i], v[2 * i + 1]);
        float l0 = v[2 * i]     - __low2float(h);
        float l1 = v[2 * i + 1] - __high2float(h);
        __nv_bfloat162 l = __floats2bfloat162_rn(l0, l1);
        H[i] = *reinterpret_cast<uint32_t*>(&h);
        L[i] = *reinterpret_cast<uint32_t*>(&l);
    }
    *reinterpret_cast<uint4*>(hib + sw) = make_uint4(H[0], H[1], H[2], H[3]);
    *reinterpret_cast<uint4*>(lob + sw) = make_uint4(L[0], L[1], L[2], L[3]);
}
// packed pair store: (c,c+1), c even
__device__ __forceinline__ void stA2(char* a_t, int r, int c, float v0, float v1)
{
    int kt = c >> 6;
    uint32_t sw = swz(r * 128 + (c & 63) * 2);
    __nv_bfloat162 h = __floats2bfloat162_rn(v0, v1);
    float l0 = v0 - __low2float(h);
    float l1 = v1 - __high2float(h);
    __nv_bfloat162 l = __floats2bfloat162_rn(l0, l1);
    *reinterpret_cast<uint32_t*>(a_t + kt * 16384 + sw) = *reinterpret_cast<uint32_t*>(&h);
    *reinterpret_cast<uint32_t*>(a_t + 32768 + kt * 16384 + sw) = *reinterpret_cast<uint32_t*>(&l);
}

// ============================================================
// warp-level split-bf16 GEMM: warp computes rows [m0,m0+16) x
// cols [n0,n0+64) of D[128,128] = A @ W^T, 3 passes.
// B fragments loaded pairwise with ldmatrix.x4.
// ============================================================
__device__ __forceinline__ void run_gemm_mma(
    uint32_t aB, uint32_t wB, int m0, int n0, int lane, float acc[8][4])
{
    #pragma unroll
    for (int ni = 0; ni < 8; ni++)
        #pragma unroll
        for (int e = 0; e < 4; e++) acc[ni][e] = 0.f;

    int gsel   = lane >> 3;              // 0..3: (ni-pair half, k-half)
    int b_nrow = (gsel >> 1) * 8 + (lane & 7);
    int b_koff = (gsel & 1) * 16;

    #pragma unroll
    for (int p = 0; p < 3; p++) {
        uint32_t aPB = aB + ((p == 2) ? 32768u : 0u);
        uint32_t wPB = wB + ((p == 1) ? 32768u : 0u);
        #pragma unroll
        for (int kt = 0; kt < 2; kt++) {
            uint32_t aT = aPB + kt * 16384;
            uint32_t wT = wPB + kt * 16384;
            #pragma unroll
            for (int ks = 0; ks < 4; ks++) {
                uint32_t a[4];
                int row = m0 + (lane & 15);
                int kb  = ks * 32 + ((lane >> 4) << 4);
                ldm4(a, aT + swz(row * 128 + kb));
                #pragma unroll
                for (int nj = 0; nj < 4; nj++) {
                    int nrow = n0 + nj * 16 + b_nrow;
                    uint32_t b[4];
                    ldm4(b, wT + swz(nrow * 128 + ks * 32 + b_koff));
                    mma16816(acc[nj * 2],     a, b);
                    mma16816(acc[nj * 2 + 1], a, b + 2);
                }
            }
        }
    }
}

// ============================================================
// main kernel: 8 points (128 rows) / block, 512 threads,
// HMMA GEMMs, E in registers, K/V/q staged via cp.async.
// ============================================================
__global__ void __launch_bounds__(512, 1) main_kernel(
    const float* __restrict__ xyz,  const float* __restrict__ features,
    const float* __restrict__ Wd1,  const float* __restrict__ bd1,
    const float* __restrict__ bd2,
    const float* __restrict__ bg1,  const float* __restrict__ bg2,
    const float* __restrict__ Wo,   const float* __restrict__ bo,
    float* __restrict__ out)
{
    extern __shared__ char dsm[];
    uint32_t dbase = s2u(dsm);
    uint32_t pad = (1024u - (dbase & 1023u)) & 1023u;
    char*  a_t  = dsm + pad;                   // 4 x 16KB (hi0,hi1,lo0,lo1)
    char*  w_t  = a_t + 65536;                 // 4 x 16KB
    float* s_kv = (float*)(w_t + 65536);       // 128 x KV_STR floats (K, then V)

    __shared__ float s_wd1[3 * DM], s_bd1[DM], s_bd2[DM], s_bg1[DM], s_bg2[DM], s_bo[DP];
    __shared__ float s_res[8 * 129];
    __shared__ float s_q[8 * DM];
    __shared__ int   s_gi[128];

    const int tid  = threadIdx.x;
    const int wid  = tid >> 5;
    const int lane = tid & 31;
    const int blk  = blockIdx.x;
    const int m0   = (wid & 7) * 16;     // warp row range (one point)
    const int n0   = (wid >> 3) * 64;    // warp col half

    // stage small weights/biases
    for (int i = tid; i < 3 * DM; i += 512) s_wd1[i] = Wd1[i];
    if (tid < DM) {
        s_bd1[tid] = bd1[tid]; s_bd2[tid] = bd2[tid];
        s_bg1[tid] = bg1[tid]; s_bg2[tid] = bg2[tid];
    }
    if (tid >= DM && tid < DM + DP) s_bo[tid - DM] = bo[tid - DM];

    // W tiles for GEMM 0
    {
        const char* src = (const char*)g_Wb;
        for (int i = tid; i < 4096; i += 512)
            cp16(w_t + i * 16, src + (size_t)i * 16);
        cp_commit();
    }

    // neighbor indices
    if (tid < 128) {
        int gp = blk * 8 + (tid >> 4);
        int bb = gp >> 12;
        int idx = g_knn[(size_t)gp * KK + (tid & 15)];
        s_gi[tid] = bb * Nn + idx;
    }
    __syncthreads();   // s_gi visible

    // stage K rows (gathered) + q rows via cp.async (overlaps stage1/GEMM0)
    {
        for (int i = tid; i < 4096; i += 512) {
            int row = i >> 5, seg = i & 31;
            cp16(s_kv + row * KV_STR + seg * 4,
                 g_Kf + (size_t)s_gi[row] * DM + seg * 4);
        }
        for (int i = tid; i < 256; i += 512) {
            int row = i >> 5, seg = i & 31;
            cp16(s_q + row * DM + seg * 4,
                 g_Q + (size_t)(blk * 8 + row) * DM + seg * 4);
        }
        cp_commit();
    }

    // stage 1: H = relu(rel @ Wd1 + bd1) -> A tiles (hi/lo)
    {
        int r  = tid & 127;
        int qq = tid >> 7;                  // 0..3 column quarter
        int gp = blk * 8 + (r >> 4);
        int gi = s_gi[r];
        float rx = xyz[(size_t)gp * 3 + 0] - xyz[(size_t)gi * 3 + 0];
        float ry = xyz[(size_t)gp * 3 + 1] - xyz[(size_t)gi * 3 + 1];
        float rz = xyz[(size_t)gp * 3 + 2] - xyz[(size_t)gi * 3 + 2];
        #pragma unroll
        for (int cg = 0; cg < 4; cg++) {
            int c0 = qq * 32 + cg * 8;
            float v[8];
            #pragma unroll
            for (int j = 0; j < 8; j++) {
                int c = c0 + j;
                float h = fmaf(rx, s_wd1[c], fmaf(ry, s_wd1[DM + c],
                           fmaf(rz, s_wd1[2 * DM + c], s_bd1[c])));
                v[j] = fmaxf(h, 0.f);
            }
            store8(a_t, r, c0, v);
        }
    }

    cp_wait0();        // W0 + K + q landed
    __syncthreads();   // visible to all; a_t ready

    uint32_t aB = s2u(a_t);
    uint32_t wB = s2u(w_t);
    float acc[8][4];
    float E[8][4];                        // pos_enc fragment (registers)

    // ---------------- GEMM 0: pos_enc ----------------
    run_gemm_mma(aB, wB, m0, n0, lane, acc);
    __syncthreads();                      // w_t free

    // prefetch W for GEMM 1
    {
        const char* src = (const char*)g_Wb + 65536;
        for (int i = tid; i < 4096; i += 512)
            cp16(w_t + i * 16, src + (size_t)i * 16);
        cp_commit();
    }

    // epilogue 0: E = D + bd2 (regs) ; A = q - k + E -> tiles (smem K/q)
    {
        int r0 = m0 + (lane >> 2);
        int r1 = r0 + 8;
        int pt = m0 >> 4;
        const float* qv = s_q  + pt * DM;
        const float* k0 = s_kv + r0 * KV_STR;
        const float* k1 = s_kv + r1 * KV_STR;
        #pragma unroll
        for (int ni = 0; ni < 8; ni++) {
            int c = n0 + ni * 8 + 2 * (lane & 3);
            float q0 = qv[c], q1 = qv[c + 1];
            E[ni][0] = acc[ni][0] + s_bd2[c];
            E[ni][1] = acc[ni][1] + s_bd2[c + 1];
            E[ni][2] = acc[ni][2] + s_bd2[c];
            E[ni][3] = acc[ni][3] + s_bd2[c + 1];
            stA2(a_t, r0, c, q0 - k0[c] + E[ni][0], q1 - k0[c + 1] + E[ni][1]);
            stA2(a_t, r1, c, q0 - k1[c] + E[ni][2], q1 - k1[c + 1] + E[ni][3]);
        }
    }
    cp_wait0();        // W1 landed
    __syncthreads();   // K fully consumed; a_t ready

    // stage V rows into s_kv (overlaps GEMM1/epilogue1/GEMM2)
    for (int i = tid; i < 4096; i += 512) {
        int row = i >> 5, seg = i & 31;
        cp16(s_kv + row * KV_STR + seg * 4,
             g_Vf + (size_t)s_gi[row] * DM + seg * 4);
    }
    cp_commit();

    // ---------------- GEMM 1: gamma layer 1 ----------------
    run_gemm_mma(aB, wB, m0, n0, lane, acc);
    __syncthreads();                      // w_t free

    // prefetch W for GEMM 2
    {
        const char* src = (const char*)g_Wb + 131072;
        for (int i = tid; i < 4096; i += 512)
            cp16(w_t + i * 16, src + (size_t)i * 16);
        cp_commit();
    }

    // epilogue 1: G = relu(D + bg1) -> tiles
    {
        int r0 = m0 + (lane >> 2);
        int r1 = r0 + 8;
        #pragma unroll
        for (int ni = 0; ni < 8; ni++) {
            int c = n0 + ni * 8 + 2 * (lane & 3);
            stA2(a_t, r0, c, fmaxf(acc[ni][0] + s_bg1[c],     0.f),
                             fmaxf(acc[ni][1] + s_bg1[c + 1], 0.f));
            stA2(a_t, r1, c, fmaxf(acc[ni][2] + s_bg1[c],     0.f),
                             fmaxf(acc[ni][3] + s_bg1[c + 1], 0.f));
        }
    }
    cp_wait0();        // W2 + V landed
    __syncthreads();

    // ---------------- GEMM 2: gamma layer 2 ----------------
    run_gemm_mma(aB, wB, m0, n0, lane, acc);

    // epilogue 2: softmax over the 16 k-rows of the warp's point
    // (no barrier needed: reads only own regs + V smem staged above)
    {
        const float inv_s = 0.08838834764831845f;   // 1/sqrt(128)
        int r0 = m0 + (lane >> 2);
        int r1 = r0 + 8;
        int pt = m0 >> 4;
        const float* v0r = s_kv + r0 * KV_STR;
        const float* v1r = s_kv + r1 * KV_STR;
        #pragma unroll
        for (int ni = 0; ni < 8; ni++) {
            int c = n0 + ni * 8 + 2 * (lane & 3);
            float l0 = acc[ni][0] + s_bg2[c];       // (r0, c)
            float l1 = acc[ni][1] + s_bg2[c + 1];   // (r0, c+1)
            float l2 = acc[ni][2] + s_bg2[c];       // (r1, c)
            float l3 = acc[ni][3] + s_bg2[c + 1];   // (r1, c+1)
            float mA = fmaxf(l0, l2), mB = fmaxf(l1, l3);
            #pragma unroll
            for (int off = 4; off <= 16; off <<= 1) {
                mA = fmaxf(mA, __shfl_xor_sync(0xffffffffu, mA, off));
                mB = fmaxf(mB, __shfl_xor_sync(0xffffffffu, mB, off));
            }
            float e0 = __expf((l0 - mA) * inv_s);
            float e2 = __expf((l2 - mA) * inv_s);
            float e1 = __expf((l1 - mB) * inv_s);
            float e3 = __expf((l3 - mB) * inv_s);
            float vE0 = v0r[c]     + E[ni][0];
            float vE1 = v0r[c + 1] + E[ni][1];
            float vE2 = v1r[c]     + E[ni][2];
            float vE3 = v1r[c + 1] + E[ni][3];
            float sA = e0 + e2,                sB = e1 + e3;
            float nA = fmaf(e0, vE0, e2 * vE2), nB = fmaf(e1, vE1, e3 * vE3);
            #pragma unroll
            for (int off = 4; off <= 16; off <<= 1) {
                sA += __shfl_xor_sync(0xffffffffu, sA, off);
                sB += __shfl_xor_sync(0xffffffffu, sB, off);
                nA += __shfl_xor_sync(0xffffffffu, nA, off);
                nB += __shfl_xor_sync(0xffffffffu, nB, off);
            }
            if ((lane >> 2) == 0) {
                s_res[pt * 129 + c]     = nA / sA;
                s_res[pt * 129 + c + 1] = nB / sB;
            }
        }
    }
    __syncthreads();

    // output: out = res @ Wo + bo + features   [8,64] (one elem/thread)
    {
        int pp = tid >> 6, j = tid & 63;
        float acc2 = s_bo[j];
        #pragma unroll 4
        for (int c = 0; c < DM; c++)
            acc2 = fmaf(s_res[pp * 129 + c], Wo[(size_t)c * DP + j], acc2);
        int go = blk * 8 + pp;
        out[(size_t)go * DP + j] = acc2 + features[(size_t)go * DP + j];
    }
}

// ============================================================
extern "C" void kernel_launch(void* const* d_in, const int* in_sizes, int n_in,
                              void* d_out, int out_size)
{
    (void)in_sizes; (void)n_in; (void)out_size;
    const float* xyz      = (const float*)d_in[0];
    const float* features = (const float*)d_in[1];
    const float* Wd1 = (const float*)d_in[2];
    const float* bd1 = (const float*)d_in[3];
    const float* Wd2 = (const float*)d_in[4];
    const float* bd2 = (const float*)d_in[5];
    const float* Wf1 = (const float*)d_in[6];
    const float* bf1 = (const float*)d_in[7];
    const float* Wq  = (const float*)d_in[8];
    const float* Wk  = (const float*)d_in[9];
    const float* Wv  = (const float*)d_in[10];
    const float* Wg1 = (const float*)d_in[11];
    const float* bg1 = (const float*)d_in[12];
    const float* Wg2 = (const float*)d_in[13];
    const float* bg2 = (const float*)d_in[14];
    const float* Wo  = (const float*)d_in[15];
    const float* bo  = (const float*)d_in[16];
    float* out = (float*)d_out;

    prep_w<<<6, 128>>>(Wd2, Wg1, Wg2);

    size_t sh_knn = (size_t)Nn * sizeof(float4);
    cudaFuncSetAttribute(knn_kernel,
                         cudaFuncAttributeMaxDynamicSharedMemorySize, (int)sh_knn);
    knn_kernel<<<dim3(Bb, Nn / 32), 256, sh_knn>>>(xyz);

    size_t sh_fqkv = (64 * 65 + 64 * 129 + 2048) * sizeof(float);
    cudaFuncSetAttribute(fqkv_kernel,
                         cudaFuncAttributeMaxDynamicSharedMemorySize, (int)sh_fqkv);
    fqkv_kernel<<<BN / 64, 256, sh_fqkv>>>(features, Wf1, bf1, Wq, Wk, Wv);

    size_t sh_main = 1024 + 65536 + 65536 + (size_t)128 * KV_STR * sizeof(float);
    cudaFuncSetAttribute(main_kernel,
                         cudaFuncAttributeMaxDynamicSharedMemorySize, (int)sh_main);
    main_kernel<<<BN / 8, 512, sh_main>>>(xyz, features,
                                          Wd1, bd1, bd2, bg1, bg2,
                                          Wo, bo, out);
}